// round 13
// baseline (speedup 1.0000x reference)
#include <cuda_runtime.h>
#include <cstdint>
#include <cstddef>

// Fixed problem sizes: B=2, S=2048, D=768, H=12, DK=64
constexpr int Bc  = 2;
constexpr int Sc  = 2048;
constexpr int Dc  = 768;
constexpr int Hc  = 12;
constexpr int DKc = 64;
constexpr int Mrows = Bc * Sc;   // 4096

constexpr int NQ = Mrows * Dc;   // 3145728 floats per activation tensor
constexpr int NW = Dc * Dc;      // 589824 floats per weight matrix

// Scratch (device globals: allocation-free per harness rules)
__device__ float g_tf[3 * NQ + 4 * NW];       // tf32-rounded q,k,v,Wq,Wk,Wv,Wo
__device__ float g_Q[Bc * Hc * Sc * DKc];     // [B,H,S,DK], tf32+scaled
__device__ float g_K[Bc * Hc * Sc * DKc];     // tf32
__device__ float g_V[Bc * Hc * Sc * DKc];     // tf32
__device__ float g_attn[Mrows * Dc];          // [B,S,D], tf32

// ---------------------------------------------------------------------------
// helpers
// ---------------------------------------------------------------------------
__device__ __forceinline__ float f2tf(float f) {
    uint32_t u;
    asm("cvt.rna.tf32.f32 %0, %1;" : "=r"(u) : "f"(f));
    return __uint_as_float(u);
}
__device__ __forceinline__ uint32_t fu(float f) { return __float_as_uint(f); }
__device__ __forceinline__ uint32_t sptr(const void* p) {
    return (uint32_t)__cvta_generic_to_shared(p);
}
__device__ __forceinline__ void cp16(uint32_t dst, const void* src) {
    asm volatile("cp.async.cg.shared.global [%0], [%1], 16;\n" :: "r"(dst), "l"(src));
}
__device__ __forceinline__ void cp_commit() {
    asm volatile("cp.async.commit_group;\n");
}
template <int N>
__device__ __forceinline__ void cp_wait() {
    asm volatile("cp.async.wait_group %0;\n" :: "n"(N));
}

// C += A(16x8) * B(8x8), tf32 operands, fp32 accumulate.
__device__ __forceinline__ void mma8(float* c, const uint32_t* a,
                                     uint32_t b0, uint32_t b1) {
    asm volatile(
        "mma.sync.aligned.m16n8k8.row.col.f32.tf32.tf32.f32 "
        "{%0,%1,%2,%3}, {%4,%5,%6,%7}, {%8,%9}, {%0,%1,%2,%3};\n"
        : "+f"(c[0]), "+f"(c[1]), "+f"(c[2]), "+f"(c[3])
        : "r"(a[0]), "r"(a[1]), "r"(a[2]), "r"(a[3]), "r"(b0), "r"(b1));
}

// ---------------------------------------------------------------------------
// Pre-pass: tf32-round q,k,v,Wq,Wk,Wv,Wo into g_tf (float4 grid-stride)
// ---------------------------------------------------------------------------
__global__ __launch_bounds__(256)
void prepass(const float4* __restrict__ q, const float4* __restrict__ k,
             const float4* __restrict__ v, const float4* __restrict__ wq,
             const float4* __restrict__ wk, const float4* __restrict__ wv,
             const float4* __restrict__ wo, float4* __restrict__ dst)
{
    constexpr int NQ4 = NQ / 4;
    constexpr int NW4 = NW / 4;
    constexpr int TOT = 3 * NQ4 + 4 * NW4;
    for (int i = blockIdx.x * blockDim.x + threadIdx.x; i < TOT;
         i += gridDim.x * blockDim.x) {
        const float4* src; int off;
        if (i < NQ4)            { src = q;  off = i; }
        else if (i < 2 * NQ4)   { src = k;  off = i - NQ4; }
        else if (i < 3 * NQ4)   { src = v;  off = i - 2 * NQ4; }
        else {
            int j = i - 3 * NQ4;
            int w = j / NW4; off = j - w * NW4;
            src = (w == 0) ? wq : (w == 1) ? wk : (w == 2) ? wv : wo;
        }
        float4 x = src[off];
        dst[i] = {f2tf(x.x), f2tf(x.y), f2tf(x.z), f2tf(x.w)};
    }
}

// ---------------------------------------------------------------------------
// GEMM core (tf32 tensor cores, cp.async double-buffered):
// Block 128x128x16, 256 threads = 8 warps (2x4), warp tile 64x32.
// EPI 0: head-split [B,H,S,DK], tf32 out   (K/V projections)
// EPI 2: head-split, * rsqrt(768), tf32 out (Q projection)
// EPI 1: row-major, ReLU, fp32 out          (final)
// ---------------------------------------------------------------------------
struct GemmSmem {
    float As[2][128][20];
    float Bs[2][16][136];
};

__device__ __forceinline__
void gemm_body(const float* __restrict__ X, const float* __restrict__ W,
               const float* __restrict__ bias, float* __restrict__ out,
               int m0, int n0, int epi, GemmSmem& S)
{
    const int tid  = threadIdx.x;
    const int lane = tid & 31;
    const int warp = tid >> 5;
    const int lq   = lane >> 2;
    const int lr   = lane & 3;
    const int wm   = (warp & 1) * 64;
    const int wn   = (warp >> 1) * 32;

    const int ar = tid >> 2;
    const int ac = (tid & 3) * 4;
    const int bk = tid >> 5;
    const int bn = (tid & 31) * 4;

    auto fill = [&](int i, int buf) {
        const float* a = X + (size_t)(m0 + ar) * Dc + i * 16 + ac;
        cp16(sptr(&S.As[buf][ar][ac]), a);
        cp16(sptr(&S.As[buf][64 + ar][ac]), a + (size_t)64 * Dc);
        const float* w = W + (size_t)(i * 16 + bk) * Dc + n0 + bn;
        cp16(sptr(&S.Bs[buf][bk][bn]), w);
        cp16(sptr(&S.Bs[buf][8 + bk][bn]), w + (size_t)8 * Dc);
    };

    float c[4][4][4];
#pragma unroll
    for (int mt = 0; mt < 4; mt++)
#pragma unroll
        for (int nt = 0; nt < 4; nt++)
#pragma unroll
            for (int j = 0; j < 4; j++) c[mt][nt][j] = 0.0f;

    fill(0, 0); cp_commit();

    constexpr int NIT = Dc / 16;   // 48
    for (int i = 0; i < NIT; i++) {
        const int cur = i & 1;
        if (i < NIT - 1) { fill(i + 1, cur ^ 1); cp_commit(); cp_wait<1>(); }
        else             { cp_wait<0>(); }
        __syncthreads();

#pragma unroll
        for (int ks = 0; ks < 16; ks += 8) {
            uint32_t a[4][4], b[4][2];
#pragma unroll
            for (int mt = 0; mt < 4; mt++) {
                int r = wm + mt * 16 + lq;
                a[mt][0] = fu(S.As[cur][r][ks + lr]);
                a[mt][1] = fu(S.As[cur][r + 8][ks + lr]);
                a[mt][2] = fu(S.As[cur][r][ks + lr + 4]);
                a[mt][3] = fu(S.As[cur][r + 8][ks + lr + 4]);
            }
#pragma unroll
            for (int nt = 0; nt < 4; nt++) {
                int n = wn + nt * 8 + lq;
                b[nt][0] = fu(S.Bs[cur][ks + lr][n]);
                b[nt][1] = fu(S.Bs[cur][ks + lr + 4][n]);
            }
#pragma unroll
            for (int mt = 0; mt < 4; mt++)
#pragma unroll
                for (int nt = 0; nt < 4; nt++)
                    mma8(c[mt][nt], a[mt], b[nt][0], b[nt][1]);
        }
        __syncthreads();
    }

    const float qscale = rsqrtf((float)Dc);
#pragma unroll
    for (int mt = 0; mt < 4; mt++) {
        int r0 = m0 + wm + mt * 16 + lq;
#pragma unroll
        for (int nt = 0; nt < 4; nt++) {
            int col = n0 + wn + nt * 8 + 2 * lr;
            float2 bv = *(const float2*)&bias[col];
            const float* cc = c[mt][nt];
            if (epi != 1) {
                int h = col >> 6, dk = col & 63;
#pragma unroll
                for (int rp = 0; rp < 2; rp++) {
                    int r = r0 + rp * 8;
                    int bb = r >> 11, s = r & (Sc - 1);
                    float x0 = cc[2 * rp]     + bv.x;
                    float x1 = cc[2 * rp + 1] + bv.y;
                    if (epi == 2) { x0 *= qscale; x1 *= qscale; }
                    float2 v = {f2tf(x0), f2tf(x1)};
                    *(float2*)&out[(((size_t)(bb * Hc + h) * Sc + s) << 6) + dk] = v;
                }
            } else {
                float2 v0 = {fmaxf(cc[0] + bv.x, 0.0f), fmaxf(cc[1] + bv.y, 0.0f)};
                float2 v1 = {fmaxf(cc[2] + bv.x, 0.0f), fmaxf(cc[3] + bv.y, 0.0f)};
                *(float2*)&out[(size_t)r0 * Dc + col]       = v0;
                *(float2*)&out[(size_t)(r0 + 8) * Dc + col] = v1;
            }
        }
    }
}

// Fused Q/K/V projections in one launch: blockIdx.z selects the GEMM.
__global__ __launch_bounds__(256, 2)
void gemm_qkv(const float* __restrict__ Xq, const float* __restrict__ Xk,
              const float* __restrict__ Xv,
              const float* __restrict__ Wq, const float* __restrict__ Wk,
              const float* __restrict__ Wv,
              const float* __restrict__ bq, const float* __restrict__ bk,
              const float* __restrict__ bv,
              float* __restrict__ Oq, float* __restrict__ Ok,
              float* __restrict__ Ov)
{
    __shared__ GemmSmem S;
    const int z = blockIdx.z;
    const float* X = (z == 0) ? Xq : (z == 1) ? Xk : Xv;
    const float* W = (z == 0) ? Wq : (z == 1) ? Wk : Wv;
    const float* b = (z == 0) ? bq : (z == 1) ? bk : bv;
    float* O       = (z == 0) ? Oq : (z == 1) ? Ok : Ov;
    gemm_body(X, W, b, O, blockIdx.x * 128, blockIdx.y * 128,
              (z == 0) ? 2 : 0, S);
}

// Final projection (ReLU, fp32 out)
__global__ __launch_bounds__(256, 2)
void gemm_out(const float* __restrict__ X, const float* __restrict__ W,
              const float* __restrict__ bias, float* __restrict__ out)
{
    __shared__ GemmSmem S;
    gemm_body(X, W, bias, out, blockIdx.x * 128, blockIdx.y * 128, 1, S);
}

// ---------------------------------------------------------------------------
// Flash attention, tf32 tensor cores, cp.async double-buffered K/V.
// 256 threads = 8 warps; BQ=128 per block; warp w owns q-rows
// [q0 + 16w, q0 + 16w + 16). KV tiles of 64; warp-level causal skipping.
// Q A-fragments in registers; V natural [kv][dk] layout (== B-fragment);
// P c-frag -> A-frag via shfl (no smem round-trip).
// ---------------------------------------------------------------------------
__global__ __launch_bounds__(256, 2)
void attn_tc(const float* __restrict__ Q, const float* __restrict__ K,
             const float* __restrict__ V, float* __restrict__ O)
{
    extern __shared__ float sm[];
    float* KsB = sm;                         // [2][64][68]
    float* VsB = sm + 2 * 64 * 68;           // [2][64][72]
#define KS(b, r, c) KsB[(b) * 4352 + (r) * 68 + (c)]
#define VS(b, r, c) VsB[(b) * 4608 + (r) * 72 + (c)]

    const int tid  = threadIdx.x;
    const int lane = tid & 31;
    const int warp = tid >> 5;               // 0..7
    const int lq   = lane >> 2;
    const int lr   = lane & 3;
    const int qb   = gridDim.x - 1 - blockIdx.x;   // long blocks first
    const int bh   = blockIdx.y;
    const int q0   = qb * 128;

    const float* Qg = Q + (size_t)bh * Sc * DKc;
    const float* Kg = K + (size_t)bh * Sc * DKc;
    const float* Vg = V + (size_t)bh * Sc * DKc;

    const int fr = tid >> 4;            // 0..15 (fill row base)
    const int fc = (tid & 15) * 4;      // 0..60 (fill col)

    auto fill = [&](int kt, int buf) {
        const float* kp = Kg + (size_t)(kt * 64 + fr) * DKc + fc;
        const float* vp = Vg + (size_t)(kt * 64 + fr) * DKc + fc;
#pragma unroll
        for (int it = 0; it < 4; it++) {
            cp16(sptr(&KS(buf, fr + it * 16, fc)), kp + (size_t)it * 16 * DKc);
            cp16(sptr(&VS(buf, fr + it * 16, fc)), vp + (size_t)it * 16 * DKc);
        }
    };

    // Q A-fragments in registers (pre-scaled + pre-tf32 by projection epilogue)
    uint32_t qa[8][4];
    {
        const float* q0p = Qg + (size_t)(q0 + warp * 16 + lq) * DKc;
        const float* q1p = q0p + (size_t)8 * DKc;
#pragma unroll
        for (int ks = 0; ks < 8; ks++) {
            qa[ks][0] = fu(q0p[ks * 8 + lr]);
            qa[ks][1] = fu(q1p[ks * 8 + lr]);
            qa[ks][2] = fu(q0p[ks * 8 + lr + 4]);
            qa[ks][3] = fu(q1p[ks * 8 + lr + 4]);
        }
    }

    float o[8][4];
#pragma unroll
    for (int nf = 0; nf < 8; nf++)
#pragma unroll
        for (int j = 0; j < 4; j++) o[nf][j] = 0.0f;
    float m_i[2] = {-1e30f, -1e30f};
    float l_i[2] = {0.0f, 0.0f};

    const int src0 = (lane & ~3) | (lr >> 1);
    const int src1 = src0 + 2;
    const bool oddl = (lr & 1) != 0;

    // Warp's diagonal KV tile; block iterates kt = 0 .. ktmax = 2*qb+1.
    const int ktd   = 2 * qb + (warp >> 2);
    const int ktmax = 2 * qb + 1;
    // Row of this warp's fragment rows within its diagonal tile:
    const int rowl  = 16 * (warp & 3) + lq;   // + 8*(j>>1) added per element

    fill(0, 0); cp_commit();

    for (int kt = 0; kt <= ktmax; kt++) {
        const int cur = kt & 1;
        if (kt < ktmax) { fill(kt + 1, cur ^ 1); cp_commit(); cp_wait<1>(); }
        else            { cp_wait<0>(); }
        __syncthreads();

        if (kt <= ktd) {
            // ---- S = Q @ K^T (warp: 16x64) ----
            float s[8][4];
#pragma unroll
            for (int nf = 0; nf < 8; nf++)
#pragma unroll
                for (int j = 0; j < 4; j++) s[nf][j] = 0.0f;

#pragma unroll
            for (int ks = 0; ks < 8; ks++) {
#pragma unroll
                for (int nf = 0; nf < 8; nf++) {
                    uint32_t b0 = fu(KS(cur, nf * 8 + lq, ks * 8 + lr));
                    uint32_t b1 = fu(KS(cur, nf * 8 + lq, ks * 8 + lr + 4));
                    mma8(s[nf], qa[ks], b0, b1);
                }
            }

            // ---- causal mask on this warp's diagonal tile ----
            if (kt == ktd) {
#pragma unroll
                for (int nf = 0; nf < 8; nf++)
#pragma unroll
                    for (int j = 0; j < 4; j++) {
                        int colg = nf * 8 + 2 * lr + (j & 1);
                        int rowg = rowl + 8 * (j >> 1);
                        if (colg > rowg) s[nf][j] = -1e30f;
                    }
            }

            // ---- online softmax (rows lq and lq+8 of the warp strip) ----
#pragma unroll
            for (int rp = 0; rp < 2; rp++) {
                float mx = -1e30f;
#pragma unroll
                for (int nf = 0; nf < 8; nf++)
                    mx = fmaxf(mx, fmaxf(s[nf][2 * rp], s[nf][2 * rp + 1]));
                mx = fmaxf(mx, __shfl_xor_sync(0xffffffffu, mx, 1));
                mx = fmaxf(mx, __shfl_xor_sync(0xffffffffu, mx, 2));
                float mnew = fmaxf(m_i[rp], mx);
                float corr = __expf(m_i[rp] - mnew);
                m_i[rp] = mnew;
                float rs = 0.0f;
#pragma unroll
                for (int nf = 0; nf < 8; nf++) {
                    float p0 = f2tf(__expf(s[nf][2 * rp]     - mnew));
                    float p1 = f2tf(__expf(s[nf][2 * rp + 1] - mnew));
                    s[nf][2 * rp]     = p0;
                    s[nf][2 * rp + 1] = p1;
                    rs += p0 + p1;
                }
                rs += __shfl_xor_sync(0xffffffffu, rs, 1);
                rs += __shfl_xor_sync(0xffffffffu, rs, 2);
                l_i[rp] = l_i[rp] * corr + rs;
#pragma unroll
                for (int nf = 0; nf < 8; nf++) {
                    o[nf][2 * rp]     *= corr;
                    o[nf][2 * rp + 1] *= corr;
                }
            }

            // ---- O += P @ V (P c-frag -> A-frag via shfl) ----
#pragma unroll
            for (int ks = 0; ks < 8; ks++) {
                float p0 = s[ks][0], p1 = s[ks][1], p2 = s[ks][2], p3 = s[ks][3];
                float t00 = __shfl_sync(0xffffffffu, p0, src0);
                float t01 = __shfl_sync(0xffffffffu, p1, src0);
                float t20 = __shfl_sync(0xffffffffu, p2, src0);
                float t21 = __shfl_sync(0xffffffffu, p3, src0);
                float u00 = __shfl_sync(0xffffffffu, p0, src1);
                float u01 = __shfl_sync(0xffffffffu, p1, src1);
                float u20 = __shfl_sync(0xffffffffu, p2, src1);
                float u21 = __shfl_sync(0xffffffffu, p3, src1);
                uint32_t pa[4];
                pa[0] = fu(oddl ? t01 : t00);
                pa[1] = fu(oddl ? t21 : t20);
                pa[2] = fu(oddl ? u01 : u00);
                pa[3] = fu(oddl ? u21 : u20);
#pragma unroll
                for (int nf = 0; nf < 8; nf++) {
                    uint32_t b0 = fu(VS(cur, ks * 8 + lr,     nf * 8 + lq));
                    uint32_t b1 = fu(VS(cur, ks * 8 + lr + 4, nf * 8 + lq));
                    mma8(o[nf], pa, b0, b1);
                }
            }
        }
        __syncthreads();   // protect buffer the NEXT iter's fill overwrites
    }

    // ---- normalize, write merged-head [B,S,D] (tf32 for the final GEMM) ----
    const int b = bh / Hc, h = bh % Hc;
#pragma unroll
    for (int rp = 0; rp < 2; rp++) {
        float inv = 1.0f / l_i[rp];
        int row = q0 + warp * 16 + lq + rp * 8;
        float* dst = O + ((size_t)(b * Sc + row)) * Dc + h * DKc;
#pragma unroll
        for (int nf = 0; nf < 8; nf++) {
            float2 v = {f2tf(o[nf][2 * rp] * inv), f2tf(o[nf][2 * rp + 1] * inv)};
            *(float2*)&dst[nf * 8 + 2 * lr] = v;
        }
    }
#undef KS
#undef VS
}

// ---------------------------------------------------------------------------
// Launch
// ---------------------------------------------------------------------------
extern "C" void kernel_launch(void* const* d_in, const int* in_sizes, int n_in,
                              void* d_out, int out_size)
{
    (void)in_sizes; (void)n_in; (void)out_size;

    const float* q  = (const float*)d_in[0];
    const float* k  = (const float*)d_in[1];
    const float* v  = (const float*)d_in[2];
    // d_in[3] = mask: causal tril, applied analytically
    const float* Wq = (const float*)d_in[4];
    const float* bq = (const float*)d_in[5];
    const float* Wk = (const float*)d_in[6];
    const float* bk = (const float*)d_in[7];
    const float* Wv = (const float*)d_in[8];
    const float* bv = (const float*)d_in[9];
    const float* Wo = (const float*)d_in[10];
    const float* bo = (const float*)d_in[11];

    float *gtf, *gq, *gk, *gv, *gat;
    cudaGetSymbolAddress((void**)&gtf, g_tf);
    cudaGetSymbolAddress((void**)&gq,  g_Q);
    cudaGetSymbolAddress((void**)&gk,  g_K);
    cudaGetSymbolAddress((void**)&gv,  g_V);
    cudaGetSymbolAddress((void**)&gat, g_attn);

    prepass<<<2880, 256>>>((const float4*)q, (const float4*)k, (const float4*)v,
                           (const float4*)Wq, (const float4*)Wk,
                           (const float4*)Wv, (const float4*)Wo, (float4*)gtf);

    const float* tq  = gtf;
    const float* tk  = gtf + NQ;
    const float* tv  = gtf + 2 * NQ;
    const float* tWq = gtf + 3 * NQ;
    const float* tWk = tWq + NW;
    const float* tWv = tWk + NW;
    const float* tWo = tWv + NW;

    // Fused Q/K/V projections: 32 x 6 x 3 = 576 blocks
    gemm_qkv<<<dim3(Mrows / 128, Dc / 128, 3), 256>>>(
        tq, tk, tv, tWq, tWk, tWv, bq, bk, bv, gq, gk, gv);

    const int attn_smem = (2 * 64 * 68 + 2 * 64 * 72) * (int)sizeof(float); // 71680
    cudaFuncSetAttribute(attn_tc, cudaFuncAttributeMaxDynamicSharedMemorySize, attn_smem);
    attn_tc<<<dim3(Sc / 128, Bc * Hc), 256, attn_smem>>>(gq, gk, gv, gat);

    gemm_out<<<dim3(Mrows / 128, Dc / 128), 256>>>(gat, tWo, bo, (float*)d_out);
}

// round 14
// speedup vs baseline: 1.0003x; 1.0003x over previous
#include <cuda_runtime.h>
#include <cstdint>
#include <cstddef>

// Fixed problem sizes: B=2, S=2048, D=768, H=12, DK=64
constexpr int Bc  = 2;
constexpr int Sc  = 2048;
constexpr int Dc  = 768;
constexpr int Hc  = 12;
constexpr int DKc = 64;
constexpr int Mrows = Bc * Sc;   // 4096

constexpr int NQ = Mrows * Dc;   // 3145728 floats per activation tensor
constexpr int NW = Dc * Dc;      // 589824 floats per weight matrix

// Scratch (device globals: allocation-free per harness rules)
__device__ float g_tf[3 * NQ + 4 * NW];       // tf32-rounded q,k,v,Wq,Wk,Wv,Wo
__device__ float g_Q[Bc * Hc * Sc * DKc];     // [B,H,S,DK], tf32+scaled
__device__ float g_K[Bc * Hc * Sc * DKc];     // tf32
__device__ float g_V[Bc * Hc * Sc * DKc];     // tf32
__device__ float g_attn[Mrows * Dc];          // [B,S,D], tf32

// ---------------------------------------------------------------------------
// helpers
// ---------------------------------------------------------------------------
__device__ __forceinline__ float f2tf(float f) {
    uint32_t u;
    asm("cvt.rna.tf32.f32 %0, %1;" : "=r"(u) : "f"(f));
    return __uint_as_float(u);
}
__device__ __forceinline__ uint32_t fu(float f) { return __float_as_uint(f); }
__device__ __forceinline__ uint32_t sptr(const void* p) {
    return (uint32_t)__cvta_generic_to_shared(p);
}
__device__ __forceinline__ void cp16(uint32_t dst, const void* src) {
    asm volatile("cp.async.cg.shared.global [%0], [%1], 16;\n" :: "r"(dst), "l"(src));
}
__device__ __forceinline__ void cp_commit() {
    asm volatile("cp.async.commit_group;\n");
}
template <int N>
__device__ __forceinline__ void cp_wait() {
    asm volatile("cp.async.wait_group %0;\n" :: "n"(N));
}

// C += A(16x8) * B(8x8), tf32 operands, fp32 accumulate.
__device__ __forceinline__ void mma8(float* c, const uint32_t* a,
                                     uint32_t b0, uint32_t b1) {
    asm volatile(
        "mma.sync.aligned.m16n8k8.row.col.f32.tf32.tf32.f32 "
        "{%0,%1,%2,%3}, {%4,%5,%6,%7}, {%8,%9}, {%0,%1,%2,%3};\n"
        : "+f"(c[0]), "+f"(c[1]), "+f"(c[2]), "+f"(c[3])
        : "r"(a[0]), "r"(a[1]), "r"(a[2]), "r"(a[3]), "r"(b0), "r"(b1));
}

// ---------------------------------------------------------------------------
// Pre-pass: tf32-round q,k,v,Wq,Wk,Wv,Wo into g_tf (float4 grid-stride)
// ---------------------------------------------------------------------------
__global__ __launch_bounds__(256)
void prepass(const float4* __restrict__ q, const float4* __restrict__ k,
             const float4* __restrict__ v, const float4* __restrict__ wq,
             const float4* __restrict__ wk, const float4* __restrict__ wv,
             const float4* __restrict__ wo, float4* __restrict__ dst)
{
    constexpr int NQ4 = NQ / 4;
    constexpr int NW4 = NW / 4;
    constexpr int TOT = 3 * NQ4 + 4 * NW4;
    for (int i = blockIdx.x * blockDim.x + threadIdx.x; i < TOT;
         i += gridDim.x * blockDim.x) {
        const float4* src; int off;
        if (i < NQ4)            { src = q;  off = i; }
        else if (i < 2 * NQ4)   { src = k;  off = i - NQ4; }
        else if (i < 3 * NQ4)   { src = v;  off = i - 2 * NQ4; }
        else {
            int j = i - 3 * NQ4;
            int w = j / NW4; off = j - w * NW4;
            src = (w == 0) ? wq : (w == 1) ? wk : (w == 2) ? wv : wo;
        }
        float4 x = src[off];
        dst[i] = {f2tf(x.x), f2tf(x.y), f2tf(x.z), f2tf(x.w)};
    }
}

// ---------------------------------------------------------------------------
// GEMM core (tf32 tensor cores, cp.async double-buffered):
// Block 128x128x16, 256 threads = 8 warps (2x4), warp tile 64x32.
// EPI 0: head-split [B,H,S,DK], tf32 out   (K/V projections)
// EPI 2: head-split, * rsqrt(768), tf32 out (Q projection)
// EPI 1: row-major, ReLU, fp32 out          (final)
// ---------------------------------------------------------------------------
struct GemmSmem {
    float As[2][128][20];
    float Bs[2][16][136];
};

__device__ __forceinline__
void gemm_body(const float* __restrict__ X, const float* __restrict__ W,
               const float* __restrict__ bias, float* __restrict__ out,
               int m0, int n0, int epi, GemmSmem& S)
{
    const int tid  = threadIdx.x;
    const int lane = tid & 31;
    const int warp = tid >> 5;
    const int lq   = lane >> 2;
    const int lr   = lane & 3;
    const int wm   = (warp & 1) * 64;
    const int wn   = (warp >> 1) * 32;

    const int ar = tid >> 2;
    const int ac = (tid & 3) * 4;
    const int bk = tid >> 5;
    const int bn = (tid & 31) * 4;

    auto fill = [&](int i, int buf) {
        const float* a = X + (size_t)(m0 + ar) * Dc + i * 16 + ac;
        cp16(sptr(&S.As[buf][ar][ac]), a);
        cp16(sptr(&S.As[buf][64 + ar][ac]), a + (size_t)64 * Dc);
        const float* w = W + (size_t)(i * 16 + bk) * Dc + n0 + bn;
        cp16(sptr(&S.Bs[buf][bk][bn]), w);
        cp16(sptr(&S.Bs[buf][8 + bk][bn]), w + (size_t)8 * Dc);
    };

    float c[4][4][4];
#pragma unroll
    for (int mt = 0; mt < 4; mt++)
#pragma unroll
        for (int nt = 0; nt < 4; nt++)
#pragma unroll
            for (int j = 0; j < 4; j++) c[mt][nt][j] = 0.0f;

    fill(0, 0); cp_commit();

    constexpr int NIT = Dc / 16;   // 48
    for (int i = 0; i < NIT; i++) {
        const int cur = i & 1;
        if (i < NIT - 1) { fill(i + 1, cur ^ 1); cp_commit(); cp_wait<1>(); }
        else             { cp_wait<0>(); }
        __syncthreads();

#pragma unroll
        for (int ks = 0; ks < 16; ks += 8) {
            uint32_t a[4][4], b[4][2];
#pragma unroll
            for (int mt = 0; mt < 4; mt++) {
                int r = wm + mt * 16 + lq;
                a[mt][0] = fu(S.As[cur][r][ks + lr]);
                a[mt][1] = fu(S.As[cur][r + 8][ks + lr]);
                a[mt][2] = fu(S.As[cur][r][ks + lr + 4]);
                a[mt][3] = fu(S.As[cur][r + 8][ks + lr + 4]);
            }
#pragma unroll
            for (int nt = 0; nt < 4; nt++) {
                int n = wn + nt * 8 + lq;
                b[nt][0] = fu(S.Bs[cur][ks + lr][n]);
                b[nt][1] = fu(S.Bs[cur][ks + lr + 4][n]);
            }
#pragma unroll
            for (int mt = 0; mt < 4; mt++)
#pragma unroll
                for (int nt = 0; nt < 4; nt++)
                    mma8(c[mt][nt], a[mt], b[nt][0], b[nt][1]);
        }
        __syncthreads();
    }

    const float qscale = rsqrtf((float)Dc);
#pragma unroll
    for (int mt = 0; mt < 4; mt++) {
        int r0 = m0 + wm + mt * 16 + lq;
#pragma unroll
        for (int nt = 0; nt < 4; nt++) {
            int col = n0 + wn + nt * 8 + 2 * lr;
            float2 bv = *(const float2*)&bias[col];
            const float* cc = c[mt][nt];
            if (epi != 1) {
                int h = col >> 6, dk = col & 63;
#pragma unroll
                for (int rp = 0; rp < 2; rp++) {
                    int r = r0 + rp * 8;
                    int bb = r >> 11, s = r & (Sc - 1);
                    float x0 = cc[2 * rp]     + bv.x;
                    float x1 = cc[2 * rp + 1] + bv.y;
                    if (epi == 2) { x0 *= qscale; x1 *= qscale; }
                    float2 v = {f2tf(x0), f2tf(x1)};
                    *(float2*)&out[(((size_t)(bb * Hc + h) * Sc + s) << 6) + dk] = v;
                }
            } else {
                float2 v0 = {fmaxf(cc[0] + bv.x, 0.0f), fmaxf(cc[1] + bv.y, 0.0f)};
                float2 v1 = {fmaxf(cc[2] + bv.x, 0.0f), fmaxf(cc[3] + bv.y, 0.0f)};
                *(float2*)&out[(size_t)r0 * Dc + col]       = v0;
                *(float2*)&out[(size_t)(r0 + 8) * Dc + col] = v1;
            }
        }
    }
}

// Fused Q/K/V projections in one launch: blockIdx.z selects the GEMM.
__global__ __launch_bounds__(256, 2)
void gemm_qkv(const float* __restrict__ Xq, const float* __restrict__ Xk,
              const float* __restrict__ Xv,
              const float* __restrict__ Wq, const float* __restrict__ Wk,
              const float* __restrict__ Wv,
              const float* __restrict__ bq, const float* __restrict__ bk,
              const float* __restrict__ bv,
              float* __restrict__ Oq, float* __restrict__ Ok,
              float* __restrict__ Ov)
{
    __shared__ GemmSmem S;
    const int z = blockIdx.z;
    const float* X = (z == 0) ? Xq : (z == 1) ? Xk : Xv;
    const float* W = (z == 0) ? Wq : (z == 1) ? Wk : Wv;
    const float* b = (z == 0) ? bq : (z == 1) ? bk : bv;
    float* O       = (z == 0) ? Oq : (z == 1) ? Ok : Ov;
    gemm_body(X, W, b, O, blockIdx.x * 128, blockIdx.y * 128,
              (z == 0) ? 2 : 0, S);
}

// Final projection (ReLU, fp32 out)
__global__ __launch_bounds__(256, 2)
void gemm_out(const float* __restrict__ X, const float* __restrict__ W,
              const float* __restrict__ bias, float* __restrict__ out)
{
    __shared__ GemmSmem S;
    gemm_body(X, W, bias, out, blockIdx.x * 128, blockIdx.y * 128, 1, S);
}

// ---------------------------------------------------------------------------
// Flash attention, tf32 tensor cores, cp.async double-buffered K/V.
// 256 threads = 8 warps; BQ=128 per block; warp w owns q-rows
// [q0 + 16w, q0 + 16w + 16). KV tiles of 64; warp-level causal skipping.
// Q A-fragments in registers; V natural [kv][dk] layout (== B-fragment);
// P c-frag -> A-frag via shfl (no smem round-trip).
// ---------------------------------------------------------------------------
__global__ __launch_bounds__(256, 2)
void attn_tc(const float* __restrict__ Q, const float* __restrict__ K,
             const float* __restrict__ V, float* __restrict__ O)
{
    extern __shared__ float sm[];
    float* KsB = sm;                         // [2][64][68]
    float* VsB = sm + 2 * 64 * 68;           // [2][64][72]
#define KS(b, r, c) KsB[(b) * 4352 + (r) * 68 + (c)]
#define VS(b, r, c) VsB[(b) * 4608 + (r) * 72 + (c)]

    const int tid  = threadIdx.x;
    const int lane = tid & 31;
    const int warp = tid >> 5;               // 0..7
    const int lq   = lane >> 2;
    const int lr   = lane & 3;
    const int qb   = gridDim.x - 1 - blockIdx.x;   // long blocks first
    const int bh   = blockIdx.y;
    const int q0   = qb * 128;

    const float* Qg = Q + (size_t)bh * Sc * DKc;
    const float* Kg = K + (size_t)bh * Sc * DKc;
    const float* Vg = V + (size_t)bh * Sc * DKc;

    const int fr = tid >> 4;            // 0..15 (fill row base)
    const int fc = (tid & 15) * 4;      // 0..60 (fill col)

    auto fill = [&](int kt, int buf) {
        const float* kp = Kg + (size_t)(kt * 64 + fr) * DKc + fc;
        const float* vp = Vg + (size_t)(kt * 64 + fr) * DKc + fc;
#pragma unroll
        for (int it = 0; it < 4; it++) {
            cp16(sptr(&KS(buf, fr + it * 16, fc)), kp + (size_t)it * 16 * DKc);
            cp16(sptr(&VS(buf, fr + it * 16, fc)), vp + (size_t)it * 16 * DKc);
        }
    };

    // Q A-fragments in registers (pre-scaled + pre-tf32 by projection epilogue)
    uint32_t qa[8][4];
    {
        const float* q0p = Qg + (size_t)(q0 + warp * 16 + lq) * DKc;
        const float* q1p = q0p + (size_t)8 * DKc;
#pragma unroll
        for (int ks = 0; ks < 8; ks++) {
            qa[ks][0] = fu(q0p[ks * 8 + lr]);
            qa[ks][1] = fu(q1p[ks * 8 + lr]);
            qa[ks][2] = fu(q0p[ks * 8 + lr + 4]);
            qa[ks][3] = fu(q1p[ks * 8 + lr + 4]);
        }
    }

    float o[8][4];
#pragma unroll
    for (int nf = 0; nf < 8; nf++)
#pragma unroll
        for (int j = 0; j < 4; j++) o[nf][j] = 0.0f;
    float m_i[2] = {-1e30f, -1e30f};
    float l_i[2] = {0.0f, 0.0f};

    const int src0 = (lane & ~3) | (lr >> 1);
    const int src1 = src0 + 2;
    const bool oddl = (lr & 1) != 0;

    // Warp's diagonal KV tile; block iterates kt = 0 .. ktmax = 2*qb+1.
    const int ktd   = 2 * qb + (warp >> 2);
    const int ktmax = 2 * qb + 1;
    // Row of this warp's fragment rows within its diagonal tile:
    const int rowl  = 16 * (warp & 3) + lq;   // + 8*(j>>1) added per element

    fill(0, 0); cp_commit();

    for (int kt = 0; kt <= ktmax; kt++) {
        const int cur = kt & 1;
        if (kt < ktmax) { fill(kt + 1, cur ^ 1); cp_commit(); cp_wait<1>(); }
        else            { cp_wait<0>(); }
        __syncthreads();

        if (kt <= ktd) {
            // ---- S = Q @ K^T (warp: 16x64) ----
            float s[8][4];
#pragma unroll
            for (int nf = 0; nf < 8; nf++)
#pragma unroll
                for (int j = 0; j < 4; j++) s[nf][j] = 0.0f;

#pragma unroll
            for (int ks = 0; ks < 8; ks++) {
#pragma unroll
                for (int nf = 0; nf < 8; nf++) {
                    uint32_t b0 = fu(KS(cur, nf * 8 + lq, ks * 8 + lr));
                    uint32_t b1 = fu(KS(cur, nf * 8 + lq, ks * 8 + lr + 4));
                    mma8(s[nf], qa[ks], b0, b1);
                }
            }

            // ---- causal mask on this warp's diagonal tile ----
            if (kt == ktd) {
#pragma unroll
                for (int nf = 0; nf < 8; nf++)
#pragma unroll
                    for (int j = 0; j < 4; j++) {
                        int colg = nf * 8 + 2 * lr + (j & 1);
                        int rowg = rowl + 8 * (j >> 1);
                        if (colg > rowg) s[nf][j] = -1e30f;
                    }
            }

            // ---- online softmax (rows lq and lq+8 of the warp strip) ----
#pragma unroll
            for (int rp = 0; rp < 2; rp++) {
                float mx = -1e30f;
#pragma unroll
                for (int nf = 0; nf < 8; nf++)
                    mx = fmaxf(mx, fmaxf(s[nf][2 * rp], s[nf][2 * rp + 1]));
                mx = fmaxf(mx, __shfl_xor_sync(0xffffffffu, mx, 1));
                mx = fmaxf(mx, __shfl_xor_sync(0xffffffffu, mx, 2));
                float mnew = fmaxf(m_i[rp], mx);
                float corr = __expf(m_i[rp] - mnew);
                m_i[rp] = mnew;
                float rs = 0.0f;
#pragma unroll
                for (int nf = 0; nf < 8; nf++) {
                    float p0 = f2tf(__expf(s[nf][2 * rp]     - mnew));
                    float p1 = f2tf(__expf(s[nf][2 * rp + 1] - mnew));
                    s[nf][2 * rp]     = p0;
                    s[nf][2 * rp + 1] = p1;
                    rs += p0 + p1;
                }
                rs += __shfl_xor_sync(0xffffffffu, rs, 1);
                rs += __shfl_xor_sync(0xffffffffu, rs, 2);
                l_i[rp] = l_i[rp] * corr + rs;
#pragma unroll
                for (int nf = 0; nf < 8; nf++) {
                    o[nf][2 * rp]     *= corr;
                    o[nf][2 * rp + 1] *= corr;
                }
            }

            // ---- O += P @ V (P c-frag -> A-frag via shfl) ----
#pragma unroll
            for (int ks = 0; ks < 8; ks++) {
                float p0 = s[ks][0], p1 = s[ks][1], p2 = s[ks][2], p3 = s[ks][3];
                float t00 = __shfl_sync(0xffffffffu, p0, src0);
                float t01 = __shfl_sync(0xffffffffu, p1, src0);
                float t20 = __shfl_sync(0xffffffffu, p2, src0);
                float t21 = __shfl_sync(0xffffffffu, p3, src0);
                float u00 = __shfl_sync(0xffffffffu, p0, src1);
                float u01 = __shfl_sync(0xffffffffu, p1, src1);
                float u20 = __shfl_sync(0xffffffffu, p2, src1);
                float u21 = __shfl_sync(0xffffffffu, p3, src1);
                uint32_t pa[4];
                pa[0] = fu(oddl ? t01 : t00);
                pa[1] = fu(oddl ? t21 : t20);
                pa[2] = fu(oddl ? u01 : u00);
                pa[3] = fu(oddl ? u21 : u20);
#pragma unroll
                for (int nf = 0; nf < 8; nf++) {
                    uint32_t b0 = fu(VS(cur, ks * 8 + lr,     nf * 8 + lq));
                    uint32_t b1 = fu(VS(cur, ks * 8 + lr + 4, nf * 8 + lq));
                    mma8(o[nf], pa, b0, b1);
                }
            }
        }
        __syncthreads();   // protect buffer the NEXT iter's fill overwrites
    }

    // ---- normalize, write merged-head [B,S,D] (tf32 for the final GEMM) ----
    const int b = bh / Hc, h = bh % Hc;
#pragma unroll
    for (int rp = 0; rp < 2; rp++) {
        float inv = 1.0f / l_i[rp];
        int row = q0 + warp * 16 + lq + rp * 8;
        float* dst = O + ((size_t)(b * Sc + row)) * Dc + h * DKc;
#pragma unroll
        for (int nf = 0; nf < 8; nf++) {
            float2 v = {f2tf(o[nf][2 * rp] * inv), f2tf(o[nf][2 * rp + 1] * inv)};
            *(float2*)&dst[nf * 8 + 2 * lr] = v;
        }
    }
#undef KS
#undef VS
}

// ---------------------------------------------------------------------------
// Launch
// ---------------------------------------------------------------------------
extern "C" void kernel_launch(void* const* d_in, const int* in_sizes, int n_in,
                              void* d_out, int out_size)
{
    (void)in_sizes; (void)n_in; (void)out_size;

    const float* q  = (const float*)d_in[0];
    const float* k  = (const float*)d_in[1];
    const float* v  = (const float*)d_in[2];
    // d_in[3] = mask: causal tril, applied analytically
    const float* Wq = (const float*)d_in[4];
    const float* bq = (const float*)d_in[5];
    const float* Wk = (const float*)d_in[6];
    const float* bk = (const float*)d_in[7];
    const float* Wv = (const float*)d_in[8];
    const float* bv = (const float*)d_in[9];
    const float* Wo = (const float*)d_in[10];
    const float* bo = (const float*)d_in[11];

    float *gtf, *gq, *gk, *gv, *gat;
    cudaGetSymbolAddress((void**)&gtf, g_tf);
    cudaGetSymbolAddress((void**)&gq,  g_Q);
    cudaGetSymbolAddress((void**)&gk,  g_K);
    cudaGetSymbolAddress((void**)&gv,  g_V);
    cudaGetSymbolAddress((void**)&gat, g_attn);

    prepass<<<2880, 256>>>((const float4*)q, (const float4*)k, (const float4*)v,
                           (const float4*)Wq, (const float4*)Wk,
                           (const float4*)Wv, (const float4*)Wo, (float4*)gtf);

    const float* tq  = gtf;
    const float* tk  = gtf + NQ;
    const float* tv  = gtf + 2 * NQ;
    const float* tWq = gtf + 3 * NQ;
    const float* tWk = tWq + NW;
    const float* tWv = tWk + NW;
    const float* tWo = tWv + NW;

    // Fused Q/K/V projections: 32 x 6 x 3 = 576 blocks
    gemm_qkv<<<dim3(Mrows / 128, Dc / 128, 3), 256>>>(
        tq, tk, tv, tWq, tWk, tWv, bq, bk, bv, gq, gk, gv);

    const int attn_smem = (2 * 64 * 68 + 2 * 64 * 72) * (int)sizeof(float); // 71680
    cudaFuncSetAttribute(attn_tc, cudaFuncAttributeMaxDynamicSharedMemorySize, attn_smem);
    attn_tc<<<dim3(Sc / 128, Bc * Hc), 256, attn_smem>>>(gq, gk, gv, gat);

    gemm_out<<<dim3(Mrows / 128, Dc / 128), 256>>>(gat, tWo, bo, (float*)d_out);
}

// round 15
// speedup vs baseline: 1.0793x; 1.0790x over previous
#include <cuda_runtime.h>
#include <cstdint>
#include <cstddef>

// Fixed problem sizes: B=2, S=2048, D=768, H=12, DK=64
constexpr int Bc  = 2;
constexpr int Sc  = 2048;
constexpr int Dc  = 768;
constexpr int Hc  = 12;
constexpr int DKc = 64;
constexpr int Mrows = Bc * Sc;   // 4096

constexpr int NQ = Mrows * Dc;   // 3145728 floats per activation tensor
constexpr int NW = Dc * Dc;      // 589824 floats per weight matrix

// Scratch (device globals: allocation-free per harness rules)
__device__ float g_tf[3 * NQ + 4 * NW];       // tf32-rounded q,k,v,Wq,Wk,Wv,Wo
__device__ float g_Q[Bc * Hc * Sc * DKc];     // [B,H,S,DK], tf32+scaled
__device__ float g_K[Bc * Hc * Sc * DKc];     // tf32
__device__ float g_V[Bc * Hc * Sc * DKc];     // tf32
__device__ float g_attn[Mrows * Dc];          // [B,S,D], tf32

// ---------------------------------------------------------------------------
// helpers
// ---------------------------------------------------------------------------
__device__ __forceinline__ float f2tf(float f) {
    uint32_t u;
    asm("cvt.rna.tf32.f32 %0, %1;" : "=r"(u) : "f"(f));
    return __uint_as_float(u);
}
__device__ __forceinline__ uint32_t fu(float f) { return __float_as_uint(f); }
__device__ __forceinline__ uint32_t sptr(const void* p) {
    return (uint32_t)__cvta_generic_to_shared(p);
}
__device__ __forceinline__ void cp16(uint32_t dst, const void* src) {
    asm volatile("cp.async.cg.shared.global [%0], [%1], 16;\n" :: "r"(dst), "l"(src));
}
__device__ __forceinline__ void cp_commit() {
    asm volatile("cp.async.commit_group;\n");
}
template <int N>
__device__ __forceinline__ void cp_wait() {
    asm volatile("cp.async.wait_group %0;\n" :: "n"(N));
}

// C += A(16x8) * B(8x8), tf32 operands, fp32 accumulate.
__device__ __forceinline__ void mma8(float* c, const uint32_t* a,
                                     uint32_t b0, uint32_t b1) {
    asm volatile(
        "mma.sync.aligned.m16n8k8.row.col.f32.tf32.tf32.f32 "
        "{%0,%1,%2,%3}, {%4,%5,%6,%7}, {%8,%9}, {%0,%1,%2,%3};\n"
        : "+f"(c[0]), "+f"(c[1]), "+f"(c[2]), "+f"(c[3])
        : "r"(a[0]), "r"(a[1]), "r"(a[2]), "r"(a[3]), "r"(b0), "r"(b1));
}

// ---------------------------------------------------------------------------
// Pre-pass: tf32-round q,k,v,Wq,Wk,Wv,Wo into g_tf (float4 grid-stride)
// ---------------------------------------------------------------------------
__global__ __launch_bounds__(256)
void prepass(const float4* __restrict__ q, const float4* __restrict__ k,
             const float4* __restrict__ v, const float4* __restrict__ wq,
             const float4* __restrict__ wk, const float4* __restrict__ wv,
             const float4* __restrict__ wo, float4* __restrict__ dst)
{
    constexpr int NQ4 = NQ / 4;
    constexpr int NW4 = NW / 4;
    constexpr int TOT = 3 * NQ4 + 4 * NW4;
    for (int i = blockIdx.x * blockDim.x + threadIdx.x; i < TOT;
         i += gridDim.x * blockDim.x) {
        const float4* src; int off;
        if (i < NQ4)            { src = q;  off = i; }
        else if (i < 2 * NQ4)   { src = k;  off = i - NQ4; }
        else if (i < 3 * NQ4)   { src = v;  off = i - 2 * NQ4; }
        else {
            int j = i - 3 * NQ4;
            int w = j / NW4; off = j - w * NW4;
            src = (w == 0) ? wq : (w == 1) ? wk : (w == 2) ? wv : wo;
        }
        float4 x = src[off];
        dst[i] = {f2tf(x.x), f2tf(x.y), f2tf(x.z), f2tf(x.w)};
    }
}

// ---------------------------------------------------------------------------
// GEMM core (tf32 mma, 3-stage cp.async pipeline, BK=32, 1 sync/iter).
// MT = number of 16-row m-frags per warp (4 -> BM=128, 2 -> BM=64).
// 256 threads = 8 warps laid out 2(m) x 4(n); warp tile (MT*16) x 32.
// EPI 0: head-split [B,H,S,DK], tf32 out   (K/V projections)
// EPI 2: head-split, * rsqrt(768), tf32 out (Q projection)
// EPI 1: row-major, ReLU, fp32 out          (final)
// ---------------------------------------------------------------------------
template <int MT>
__device__ __forceinline__
void gemm_body(const float* __restrict__ X, const float* __restrict__ W,
               const float* __restrict__ bias, float* __restrict__ out,
               int m0, int n0, int epi, float* sm)
{
    constexpr int BM  = MT * 32;
    constexpr int ASZ = BM * 36;       // stage size (floats), stride 36
    constexpr int BSZ = 32 * 136;      // stage size (floats), stride 136
    float* AsB = sm;                   // [3][BM][36]
    float* BsB = sm + 3 * ASZ;         // [3][32][136]
#define GA(st, r, c) AsB[(st) * ASZ + (r) * 36 + (c)]
#define GB(st, r, c) BsB[(st) * BSZ + (r) * 136 + (c)]

    const int tid  = threadIdx.x;
    const int lane = tid & 31;
    const int warp = tid >> 5;
    const int lq   = lane >> 2;
    const int lr   = lane & 3;
    const int wm   = (warp & 1) * (MT * 16);
    const int wn   = (warp >> 1) * 32;

    const int ar = tid >> 3;           // 0..31
    const int ac = (tid & 7) * 4;      // 0..28
    const int bk = tid >> 5;           // 0..7
    const int bn = (tid & 31) * 4;     // 0..124

    auto fill = [&](int i, int st) {
        const float* a = X + (size_t)(m0 + ar) * Dc + i * 32 + ac;
#pragma unroll
        for (int it = 0; it < BM / 32; it++)
            cp16(sptr(&GA(st, ar + 32 * it, ac)), a + (size_t)(32 * it) * Dc);
        const float* w = W + (size_t)(i * 32 + bk) * Dc + n0 + bn;
#pragma unroll
        for (int it = 0; it < 4; it++)
            cp16(sptr(&GB(st, bk + 8 * it, bn)), w + (size_t)(8 * it) * Dc);
    };

    float c[MT][4][4];
#pragma unroll
    for (int mt = 0; mt < MT; mt++)
#pragma unroll
        for (int nt = 0; nt < 4; nt++)
#pragma unroll
            for (int j = 0; j < 4; j++) c[mt][nt][j] = 0.0f;

    fill(0, 0); cp_commit();
    fill(1, 1); cp_commit();

    constexpr int NIT = Dc / 32;   // 24
    for (int i = 0; i < NIT; i++) {
        const int st = i % 3;
        cp_wait<1>();
        __syncthreads();
        if (i + 2 < NIT) fill(i + 2, (i + 2) % 3);
        cp_commit();   // empty group in tail keeps FIFO accounting exact

#pragma unroll
        for (int ks = 0; ks < 32; ks += 8) {
            uint32_t a[MT][4], b[4][2];
#pragma unroll
            for (int mt = 0; mt < MT; mt++) {
                int r = wm + mt * 16 + lq;
                a[mt][0] = fu(GA(st, r,     ks + lr));
                a[mt][1] = fu(GA(st, r + 8, ks + lr));
                a[mt][2] = fu(GA(st, r,     ks + lr + 4));
                a[mt][3] = fu(GA(st, r + 8, ks + lr + 4));
            }
#pragma unroll
            for (int nt = 0; nt < 4; nt++) {
                int n = wn + nt * 8 + lq;
                b[nt][0] = fu(GB(st, ks + lr,     n));
                b[nt][1] = fu(GB(st, ks + lr + 4, n));
            }
#pragma unroll
            for (int mt = 0; mt < MT; mt++)
#pragma unroll
                for (int nt = 0; nt < 4; nt++)
                    mma8(c[mt][nt], a[mt], b[nt][0], b[nt][1]);
        }
    }

    const float qscale = rsqrtf((float)Dc);
#pragma unroll
    for (int mt = 0; mt < MT; mt++) {
        int r0 = m0 + wm + mt * 16 + lq;
#pragma unroll
        for (int nt = 0; nt < 4; nt++) {
            int col = n0 + wn + nt * 8 + 2 * lr;
            float2 bv = *(const float2*)&bias[col];
            const float* cc = c[mt][nt];
            if (epi != 1) {
                int h = col >> 6, dk = col & 63;
#pragma unroll
                for (int rp = 0; rp < 2; rp++) {
                    int r = r0 + rp * 8;
                    int bb = r >> 11, s = r & (Sc - 1);
                    float x0 = cc[2 * rp]     + bv.x;
                    float x1 = cc[2 * rp + 1] + bv.y;
                    if (epi == 2) { x0 *= qscale; x1 *= qscale; }
                    float2 v = {f2tf(x0), f2tf(x1)};
                    *(float2*)&out[(((size_t)(bb * Hc + h) * Sc + s) << 6) + dk] = v;
                }
            } else {
                float2 v0 = {fmaxf(cc[0] + bv.x, 0.0f), fmaxf(cc[1] + bv.y, 0.0f)};
                float2 v1 = {fmaxf(cc[2] + bv.x, 0.0f), fmaxf(cc[3] + bv.y, 0.0f)};
                *(float2*)&out[(size_t)r0 * Dc + col]       = v0;
                *(float2*)&out[(size_t)(r0 + 8) * Dc + col] = v1;
            }
        }
    }
#undef GA
#undef GB
}

// Fused Q/K/V projections (128x128 tiles): blockIdx.z selects the GEMM.
__global__ __launch_bounds__(256, 2)
void gemm_qkv(const float* __restrict__ Xq, const float* __restrict__ Xk,
              const float* __restrict__ Xv,
              const float* __restrict__ Wq, const float* __restrict__ Wk,
              const float* __restrict__ Wv,
              const float* __restrict__ bq, const float* __restrict__ bk,
              const float* __restrict__ bv,
              float* __restrict__ Oq, float* __restrict__ Ok,
              float* __restrict__ Ov)
{
    extern __shared__ float sm[];
    const int z = blockIdx.z;
    const float* X = (z == 0) ? Xq : (z == 1) ? Xk : Xv;
    const float* W = (z == 0) ? Wq : (z == 1) ? Wk : Wv;
    const float* b = (z == 0) ? bq : (z == 1) ? bk : bv;
    float* O       = (z == 0) ? Oq : (z == 1) ? Ok : Ov;
    gemm_body<4>(X, W, b, O, blockIdx.x * 128, blockIdx.y * 128,
                 (z == 0) ? 2 : 0, sm);
}

// Final projection: 64x128 tiles (384 blocks -> better wave packing), ReLU.
__global__ __launch_bounds__(256, 2)
void gemm_out(const float* __restrict__ X, const float* __restrict__ W,
              const float* __restrict__ bias, float* __restrict__ out)
{
    extern __shared__ float sm[];
    gemm_body<2>(X, W, bias, out, blockIdx.x * 64, blockIdx.y * 128, 1, sm);
}

// ---------------------------------------------------------------------------
// Flash attention, tf32 mma, 3-stage cp.async K/V pipeline, 1 sync/tile.
// 256 threads = 8 warps; BQ=128 per block; warp w owns q-rows
// [q0 + 16w, q0 + 16w + 16). KV tiles of 64; warp-level causal skipping.
// Q A-fragments in registers; V natural [kv][dk] layout (== B-fragment);
// P c-frag -> A-frag via shfl (no smem round-trip).
// ---------------------------------------------------------------------------
__global__ __launch_bounds__(256, 2)
void attn_tc(const float* __restrict__ Q, const float* __restrict__ K,
             const float* __restrict__ V, float* __restrict__ O)
{
    extern __shared__ float sm[];
    float* KsB = sm;                         // [3][64][68]
    float* VsB = sm + 3 * 64 * 68;           // [3][64][72]
#define KS(st, r, c) KsB[(st) * 4352 + (r) * 68 + (c)]
#define VS(st, r, c) VsB[(st) * 4608 + (r) * 72 + (c)]

    const int tid  = threadIdx.x;
    const int lane = tid & 31;
    const int warp = tid >> 5;               // 0..7
    const int lq   = lane >> 2;
    const int lr   = lane & 3;
    const int qb   = gridDim.x - 1 - blockIdx.x;   // long blocks first
    const int bh   = blockIdx.y;
    const int q0   = qb * 128;

    const float* Qg = Q + (size_t)bh * Sc * DKc;
    const float* Kg = K + (size_t)bh * Sc * DKc;
    const float* Vg = V + (size_t)bh * Sc * DKc;

    const int fr = tid >> 4;            // 0..15 (fill row base)
    const int fc = (tid & 15) * 4;      // 0..60 (fill col)

    auto fill = [&](int kt, int st) {
        const float* kp = Kg + (size_t)(kt * 64 + fr) * DKc + fc;
        const float* vp = Vg + (size_t)(kt * 64 + fr) * DKc + fc;
#pragma unroll
        for (int it = 0; it < 4; it++) {
            cp16(sptr(&KS(st, fr + it * 16, fc)), kp + (size_t)it * 16 * DKc);
            cp16(sptr(&VS(st, fr + it * 16, fc)), vp + (size_t)it * 16 * DKc);
        }
    };

    // Q A-fragments in registers (pre-scaled + pre-tf32 by projection epilogue)
    uint32_t qa[8][4];
    {
        const float* q0p = Qg + (size_t)(q0 + warp * 16 + lq) * DKc;
        const float* q1p = q0p + (size_t)8 * DKc;
#pragma unroll
        for (int ks = 0; ks < 8; ks++) {
            qa[ks][0] = fu(q0p[ks * 8 + lr]);
            qa[ks][1] = fu(q1p[ks * 8 + lr]);
            qa[ks][2] = fu(q0p[ks * 8 + lr + 4]);
            qa[ks][3] = fu(q1p[ks * 8 + lr + 4]);
        }
    }

    float o[8][4];
#pragma unroll
    for (int nf = 0; nf < 8; nf++)
#pragma unroll
        for (int j = 0; j < 4; j++) o[nf][j] = 0.0f;
    float m_i[2] = {-1e30f, -1e30f};
    float l_i[2] = {0.0f, 0.0f};

    const int src0 = (lane & ~3) | (lr >> 1);
    const int src1 = src0 + 2;
    const bool oddl = (lr & 1) != 0;

    // Warp's diagonal KV tile; block iterates kt = 0 .. ktmax = 2*qb+1 (>=1).
    const int ktd   = 2 * qb + (warp >> 2);
    const int ktmax = 2 * qb + 1;
    const int rowl  = 16 * (warp & 3) + lq;

    fill(0, 0); cp_commit();
    fill(1, 1); cp_commit();

    for (int kt = 0; kt <= ktmax; kt++) {
        const int st = kt % 3;
        cp_wait<1>();
        __syncthreads();
        if (kt + 2 <= ktmax) fill(kt + 2, (kt + 2) % 3);
        cp_commit();   // empty group in tail keeps FIFO accounting exact

        if (kt <= ktd) {
            // ---- S = Q @ K^T (warp: 16x64) ----
            float s[8][4];
#pragma unroll
            for (int nf = 0; nf < 8; nf++)
#pragma unroll
                for (int j = 0; j < 4; j++) s[nf][j] = 0.0f;

#pragma unroll
            for (int ks = 0; ks < 8; ks++) {
#pragma unroll
                for (int nf = 0; nf < 8; nf++) {
                    uint32_t b0 = fu(KS(st, nf * 8 + lq, ks * 8 + lr));
                    uint32_t b1 = fu(KS(st, nf * 8 + lq, ks * 8 + lr + 4));
                    mma8(s[nf], qa[ks], b0, b1);
                }
            }

            // ---- causal mask on this warp's diagonal tile ----
            if (kt == ktd) {
#pragma unroll
                for (int nf = 0; nf < 8; nf++)
#pragma unroll
                    for (int j = 0; j < 4; j++) {
                        int colg = nf * 8 + 2 * lr + (j & 1);
                        int rowg = rowl + 8 * (j >> 1);
                        if (colg > rowg) s[nf][j] = -1e30f;
                    }
            }

            // ---- online softmax (rows lq and lq+8 of the warp strip) ----
#pragma unroll
            for (int rp = 0; rp < 2; rp++) {
                float mx = -1e30f;
#pragma unroll
                for (int nf = 0; nf < 8; nf++)
                    mx = fmaxf(mx, fmaxf(s[nf][2 * rp], s[nf][2 * rp + 1]));
                mx = fmaxf(mx, __shfl_xor_sync(0xffffffffu, mx, 1));
                mx = fmaxf(mx, __shfl_xor_sync(0xffffffffu, mx, 2));
                float mnew = fmaxf(m_i[rp], mx);
                float corr = __expf(m_i[rp] - mnew);
                m_i[rp] = mnew;
                float rs = 0.0f;
#pragma unroll
                for (int nf = 0; nf < 8; nf++) {
                    float p0 = f2tf(__expf(s[nf][2 * rp]     - mnew));
                    float p1 = f2tf(__expf(s[nf][2 * rp + 1] - mnew));
                    s[nf][2 * rp]     = p0;
                    s[nf][2 * rp + 1] = p1;
                    rs += p0 + p1;
                }
                rs += __shfl_xor_sync(0xffffffffu, rs, 1);
                rs += __shfl_xor_sync(0xffffffffu, rs, 2);
                l_i[rp] = l_i[rp] * corr + rs;
#pragma unroll
                for (int nf = 0; nf < 8; nf++) {
                    o[nf][2 * rp]     *= corr;
                    o[nf][2 * rp + 1] *= corr;
                }
            }

            // ---- O += P @ V (P c-frag -> A-frag via shfl) ----
#pragma unroll
            for (int ks = 0; ks < 8; ks++) {
                float p0 = s[ks][0], p1 = s[ks][1], p2 = s[ks][2], p3 = s[ks][3];
                float t00 = __shfl_sync(0xffffffffu, p0, src0);
                float t01 = __shfl_sync(0xffffffffu, p1, src0);
                float t20 = __shfl_sync(0xffffffffu, p2, src0);
                float t21 = __shfl_sync(0xffffffffu, p3, src0);
                float u00 = __shfl_sync(0xffffffffu, p0, src1);
                float u01 = __shfl_sync(0xffffffffu, p1, src1);
                float u20 = __shfl_sync(0xffffffffu, p2, src1);
                float u21 = __shfl_sync(0xffffffffu, p3, src1);
                uint32_t pa[4];
                pa[0] = fu(oddl ? t01 : t00);
                pa[1] = fu(oddl ? t21 : t20);
                pa[2] = fu(oddl ? u01 : u00);
                pa[3] = fu(oddl ? u21 : u20);
#pragma unroll
                for (int nf = 0; nf < 8; nf++) {
                    uint32_t b0 = fu(VS(st, ks * 8 + lr,     nf * 8 + lq));
                    uint32_t b1 = fu(VS(st, ks * 8 + lr + 4, nf * 8 + lq));
                    mma8(o[nf], pa, b0, b1);
                }
            }
        }
    }

    // ---- normalize, write merged-head [B,S,D] (tf32 for the final GEMM) ----
    const int b = bh / Hc, h = bh % Hc;
#pragma unroll
    for (int rp = 0; rp < 2; rp++) {
        float inv = 1.0f / l_i[rp];
        int row = q0 + warp * 16 + lq + rp * 8;
        float* dst = O + ((size_t)(b * Sc + row)) * Dc + h * DKc;
#pragma unroll
        for (int nf = 0; nf < 8; nf++) {
            float2 v = {f2tf(o[nf][2 * rp] * inv), f2tf(o[nf][2 * rp + 1] * inv)};
            *(float2*)&dst[nf * 8 + 2 * lr] = v;
        }
    }
#undef KS
#undef VS
}

// ---------------------------------------------------------------------------
// Launch
// ---------------------------------------------------------------------------
extern "C" void kernel_launch(void* const* d_in, const int* in_sizes, int n_in,
                              void* d_out, int out_size)
{
    (void)in_sizes; (void)n_in; (void)out_size;

    const float* q  = (const float*)d_in[0];
    const float* k  = (const float*)d_in[1];
    const float* v  = (const float*)d_in[2];
    // d_in[3] = mask: causal tril, applied analytically
    const float* Wq = (const float*)d_in[4];
    const float* bq = (const float*)d_in[5];
    const float* Wk = (const float*)d_in[6];
    const float* bk = (const float*)d_in[7];
    const float* Wv = (const float*)d_in[8];
    const float* bv = (const float*)d_in[9];
    const float* Wo = (const float*)d_in[10];
    const float* bo = (const float*)d_in[11];

    float *gtf, *gq, *gk, *gv, *gat;
    cudaGetSymbolAddress((void**)&gtf, g_tf);
    cudaGetSymbolAddress((void**)&gq,  g_Q);
    cudaGetSymbolAddress((void**)&gk,  g_K);
    cudaGetSymbolAddress((void**)&gv,  g_V);
    cudaGetSymbolAddress((void**)&gat, g_attn);

    prepass<<<2880, 256>>>((const float4*)q, (const float4*)k, (const float4*)v,
                           (const float4*)Wq, (const float4*)Wk,
                           (const float4*)Wv, (const float4*)Wo, (float4*)gtf);

    const float* tq  = gtf;
    const float* tk  = gtf + NQ;
    const float* tv  = gtf + 2 * NQ;
    const float* tWq = gtf + 3 * NQ;
    const float* tWk = tWq + NW;
    const float* tWv = tWk + NW;
    const float* tWo = tWv + NW;

    // smem sizes (3-stage pipelines)
    const int gsm4 = 3 * (128 * 36 + 32 * 136) * (int)sizeof(float); // 107520
    const int gsm2 = 3 * (64 * 36 + 32 * 136) * (int)sizeof(float);  // 79872
    const int asm3 = 3 * (64 * 68 + 64 * 72) * (int)sizeof(float);   // 107520

    cudaFuncSetAttribute(gemm_qkv, cudaFuncAttributeMaxDynamicSharedMemorySize, gsm4);
    cudaFuncSetAttribute(gemm_out, cudaFuncAttributeMaxDynamicSharedMemorySize, gsm2);
    cudaFuncSetAttribute(attn_tc,  cudaFuncAttributeMaxDynamicSharedMemorySize, asm3);

    // Fused Q/K/V projections: 32 x 6 x 3 = 576 blocks
    gemm_qkv<<<dim3(Mrows / 128, Dc / 128, 3), 256, gsm4>>>(
        tq, tk, tv, tWq, tWk, tWv, bq, bk, bv, gq, gk, gv);

    attn_tc<<<dim3(Sc / 128, Bc * Hc), 256, asm3>>>(gq, gk, gv, gat);

    // Final projection: 64 x 6 = 384 blocks (better wave packing)
    gemm_out<<<dim3(Mrows / 64, Dc / 128), 256, gsm2>>>(gat, tWo, bo, (float*)d_out);
}

// round 16
// speedup vs baseline: 1.1727x; 1.0865x over previous
#include <cuda_runtime.h>
#include <cstdint>
#include <cstddef>

// Fixed problem sizes: B=2, S=2048, D=768, H=12, DK=64
constexpr int Bc  = 2;
constexpr int Sc  = 2048;
constexpr int Dc  = 768;
constexpr int Hc  = 12;
constexpr int DKc = 64;
constexpr int Mrows = Bc * Sc;   // 4096

constexpr int NQ = Mrows * Dc;   // 3145728 floats per activation tensor
constexpr int NW = Dc * Dc;      // 589824 floats per weight matrix

// Scratch (device globals: allocation-free per harness rules)
__device__ float g_tf[3 * NQ + 4 * NW];       // tf32-rounded q,k,v,Wq,Wk,Wv,Wo
__device__ float g_Q[Bc * Hc * Sc * DKc];     // [B,H,S,DK], tf32+scaled
__device__ float g_K[Bc * Hc * Sc * DKc];     // tf32
__device__ float g_V[Bc * Hc * Sc * DKc];     // tf32
__device__ float g_attn[Mrows * Dc];          // [B,S,D], tf32

// ---------------------------------------------------------------------------
// helpers
// ---------------------------------------------------------------------------
__device__ __forceinline__ float f2tf(float f) {
    uint32_t u;
    asm("cvt.rna.tf32.f32 %0, %1;" : "=r"(u) : "f"(f));
    return __uint_as_float(u);
}
__device__ __forceinline__ uint32_t fu(float f) { return __float_as_uint(f); }
__device__ __forceinline__ uint32_t sptr(const void* p) {
    return (uint32_t)__cvta_generic_to_shared(p);
}
__device__ __forceinline__ void cp16(uint32_t dst, const void* src) {
    asm volatile("cp.async.cg.shared.global [%0], [%1], 16;\n" :: "r"(dst), "l"(src));
}
__device__ __forceinline__ void cp_commit() {
    asm volatile("cp.async.commit_group;\n");
}
template <int N>
__device__ __forceinline__ void cp_wait() {
    asm volatile("cp.async.wait_group %0;\n" :: "n"(N));
}

// C += A(16x8) * B(8x8), tf32 operands, fp32 accumulate.
__device__ __forceinline__ void mma8(float* c, const uint32_t* a,
                                     uint32_t b0, uint32_t b1) {
    asm volatile(
        "mma.sync.aligned.m16n8k8.row.col.f32.tf32.tf32.f32 "
        "{%0,%1,%2,%3}, {%4,%5,%6,%7}, {%8,%9}, {%0,%1,%2,%3};\n"
        : "+f"(c[0]), "+f"(c[1]), "+f"(c[2]), "+f"(c[3])
        : "r"(a[0]), "r"(a[1]), "r"(a[2]), "r"(a[3]), "r"(b0), "r"(b1));
}

// ---------------------------------------------------------------------------
// Pre-pass: tf32-round q,k,v,Wq,Wk,Wv,Wo into g_tf (float4 grid-stride)
// ---------------------------------------------------------------------------
__global__ __launch_bounds__(256)
void prepass(const float4* __restrict__ q, const float4* __restrict__ k,
             const float4* __restrict__ v, const float4* __restrict__ wq,
             const float4* __restrict__ wk, const float4* __restrict__ wv,
             const float4* __restrict__ wo, float4* __restrict__ dst)
{
    constexpr int NQ4 = NQ / 4;
    constexpr int NW4 = NW / 4;
    constexpr int TOT = 3 * NQ4 + 4 * NW4;
    for (int i = blockIdx.x * blockDim.x + threadIdx.x; i < TOT;
         i += gridDim.x * blockDim.x) {
        const float4* src; int off;
        if (i < NQ4)            { src = q;  off = i; }
        else if (i < 2 * NQ4)   { src = k;  off = i - NQ4; }
        else if (i < 3 * NQ4)   { src = v;  off = i - 2 * NQ4; }
        else {
            int j = i - 3 * NQ4;
            int w = j / NW4; off = j - w * NW4;
            src = (w == 0) ? wq : (w == 1) ? wk : (w == 2) ? wv : wo;
        }
        float4 x = src[off];
        dst[i] = {f2tf(x.x), f2tf(x.y), f2tf(x.z), f2tf(x.w)};
    }
}

// ---------------------------------------------------------------------------
// GEMM core (tf32 mma, 2-stage cp.async, BK=32, 1 sync/iter).
// 128 threads = 4 warps laid out 2(m) x 2(n); warp tile (MT*16) x 64.
// MT=4 -> BM=128 (qkv), MT=2 -> BM=64 (final).
// EPI 0: head-split [B,H,S,DK], tf32 out   (K/V projections)
// EPI 2: head-split, * rsqrt(768), tf32 out (Q projection)
// EPI 1: row-major, ReLU, fp32 out          (final)
// ---------------------------------------------------------------------------
template <int MT>
__device__ __forceinline__
void gemm_body(const float* __restrict__ X, const float* __restrict__ W,
               const float* __restrict__ bias, float* __restrict__ out,
               int m0, int n0, int epi, float* sm)
{
    constexpr int BM  = MT * 32;
    constexpr int ASZ = BM * 36;       // stage size (floats), A stride 36
    constexpr int BSZ = 32 * 136;      // stage size (floats), B stride 136
    float* AsB = sm;                   // [2][BM][36]
    float* BsB = sm + 2 * ASZ;         // [2][32][136]
#define GA(st, r, c) AsB[(st) * ASZ + (r) * 36 + (c)]
#define GB(st, r, c) BsB[(st) * BSZ + (r) * 136 + (c)]

    const int tid  = threadIdx.x;
    const int lane = tid & 31;
    const int warp = tid >> 5;          // 0..3
    const int lq   = lane >> 2;
    const int lr   = lane & 3;
    const int wm   = (warp & 1) * (MT * 16);
    const int wn   = (warp >> 1) * 64;

    auto fill = [&](int i, int st) {
        // A: BM x 32 floats = BM*8 float4 chunks over 128 threads
#pragma unroll
        for (int it = 0; it < BM / 16; it++) {
            int idx = tid + it * 128;
            int r = idx >> 3, c = (idx & 7) * 4;
            cp16(sptr(&GA(st, r, c)), X + (size_t)(m0 + r) * Dc + i * 32 + c);
        }
        // B: 32 x 128 floats = 1024 float4 chunks over 128 threads
#pragma unroll
        for (int it = 0; it < 8; it++) {
            int idx = tid + it * 128;
            int kk = idx >> 5, n = (idx & 31) * 4;
            cp16(sptr(&GB(st, kk, n)), W + (size_t)(i * 32 + kk) * Dc + n0 + n);
        }
    };

    float c[MT][8][4];
#pragma unroll
    for (int mt = 0; mt < MT; mt++)
#pragma unroll
        for (int nt = 0; nt < 8; nt++)
#pragma unroll
            for (int j = 0; j < 4; j++) c[mt][nt][j] = 0.0f;

    fill(0, 0); cp_commit();

    constexpr int NIT = Dc / 32;   // 24
    for (int i = 0; i < NIT; i++) {
        const int st = i & 1;
        cp_wait<0>();
        __syncthreads();
        if (i + 1 < NIT) { fill(i + 1, st ^ 1); cp_commit(); }

#pragma unroll
        for (int ks = 0; ks < 32; ks += 8) {
            uint32_t a[MT][4], b[8][2];
#pragma unroll
            for (int mt = 0; mt < MT; mt++) {
                int r = wm + mt * 16 + lq;
                a[mt][0] = fu(GA(st, r,     ks + lr));
                a[mt][1] = fu(GA(st, r + 8, ks + lr));
                a[mt][2] = fu(GA(st, r,     ks + lr + 4));
                a[mt][3] = fu(GA(st, r + 8, ks + lr + 4));
            }
#pragma unroll
            for (int nt = 0; nt < 8; nt++) {
                int n = wn + nt * 8 + lq;
                b[nt][0] = fu(GB(st, ks + lr,     n));
                b[nt][1] = fu(GB(st, ks + lr + 4, n));
            }
#pragma unroll
            for (int mt = 0; mt < MT; mt++)
#pragma unroll
                for (int nt = 0; nt < 8; nt++)
                    mma8(c[mt][nt], a[mt], b[nt][0], b[nt][1]);
        }
    }

    const float qscale = rsqrtf((float)Dc);
#pragma unroll
    for (int mt = 0; mt < MT; mt++) {
        int r0 = m0 + wm + mt * 16 + lq;
#pragma unroll
        for (int nt = 0; nt < 8; nt++) {
            int col = n0 + wn + nt * 8 + 2 * lr;
            float2 bv = *(const float2*)&bias[col];
            const float* cc = c[mt][nt];
            if (epi != 1) {
                int h = col >> 6, dk = col & 63;
#pragma unroll
                for (int rp = 0; rp < 2; rp++) {
                    int r = r0 + rp * 8;
                    int bb = r >> 11, s = r & (Sc - 1);
                    float x0 = cc[2 * rp]     + bv.x;
                    float x1 = cc[2 * rp + 1] + bv.y;
                    if (epi == 2) { x0 *= qscale; x1 *= qscale; }
                    float2 v = {f2tf(x0), f2tf(x1)};
                    *(float2*)&out[(((size_t)(bb * Hc + h) * Sc + s) << 6) + dk] = v;
                }
            } else {
                float2 v0 = {fmaxf(cc[0] + bv.x, 0.0f), fmaxf(cc[1] + bv.y, 0.0f)};
                float2 v1 = {fmaxf(cc[2] + bv.x, 0.0f), fmaxf(cc[3] + bv.y, 0.0f)};
                *(float2*)&out[(size_t)r0 * Dc + col]       = v0;
                *(float2*)&out[(size_t)(r0 + 8) * Dc + col] = v1;
            }
        }
    }
#undef GA
#undef GB
}

// Fused Q/K/V projections (128x128 tiles): blockIdx.z selects the GEMM.
__global__ __launch_bounds__(128, 2)
void gemm_qkv(const float* __restrict__ Xq, const float* __restrict__ Xk,
              const float* __restrict__ Xv,
              const float* __restrict__ Wq, const float* __restrict__ Wk,
              const float* __restrict__ Wv,
              const float* __restrict__ bq, const float* __restrict__ bk,
              const float* __restrict__ bv,
              float* __restrict__ Oq, float* __restrict__ Ok,
              float* __restrict__ Ov)
{
    extern __shared__ float sm[];
    const int z = blockIdx.z;
    const float* X = (z == 0) ? Xq : (z == 1) ? Xk : Xv;
    const float* W = (z == 0) ? Wq : (z == 1) ? Wk : Wv;
    const float* b = (z == 0) ? bq : (z == 1) ? bk : bv;
    float* O       = (z == 0) ? Oq : (z == 1) ? Ok : Ov;
    gemm_body<4>(X, W, b, O, blockIdx.x * 128, blockIdx.y * 128,
                 (z == 0) ? 2 : 0, sm);
}

// Final projection: 64x128 tiles, 3 CTAs/SM -> 384 blocks in one wave. ReLU.
__global__ __launch_bounds__(128, 3)
void gemm_out(const float* __restrict__ X, const float* __restrict__ W,
              const float* __restrict__ bias, float* __restrict__ out)
{
    extern __shared__ float sm[];
    gemm_body<2>(X, W, bias, out, blockIdx.x * 64, blockIdx.y * 128, 1, sm);
}

// ---------------------------------------------------------------------------
// Flash attention, tf32 mma, 2-stage cp.async K/V, 1 sync/tile.
// 128 threads = 4 warps; BQ=128; warp w owns q-rows [q0+32w, q0+32w+32)
// as two 16-row m-frags. Q A-fragments in registers; KV tiles of 64;
// warp-level causal skipping; V natural [kv][dk] layout (== B-fragment);
// P c-frag -> A-frag via shfl (no smem round-trip).
// ---------------------------------------------------------------------------
__global__ __launch_bounds__(128, 2)
void attn_tc(const float* __restrict__ Q, const float* __restrict__ K,
             const float* __restrict__ V, float* __restrict__ O)
{
    extern __shared__ float sm[];
    float* KsB = sm;                         // [2][64][68]
    float* VsB = sm + 2 * 64 * 68;           // [2][64][72]
#define KS(st, r, c) KsB[(st) * 4352 + (r) * 68 + (c)]
#define VS(st, r, c) VsB[(st) * 4608 + (r) * 72 + (c)]

    const int tid  = threadIdx.x;
    const int lane = tid & 31;
    const int warp = tid >> 5;               // 0..3
    const int lq   = lane >> 2;
    const int lr   = lane & 3;
    const int qb   = gridDim.x - 1 - blockIdx.x;   // long blocks first
    const int bh   = blockIdx.y;
    const int q0   = qb * 128;

    const float* Qg = Q + (size_t)bh * Sc * DKc;
    const float* Kg = K + (size_t)bh * Sc * DKc;
    const float* Vg = V + (size_t)bh * Sc * DKc;

    const int fr = tid >> 4;            // 0..7  (fill row base)
    const int fc = (tid & 15) * 4;      // 0..60 (fill col)

    auto fill = [&](int kt, int st) {
        const float* kp = Kg + (size_t)(kt * 64 + fr) * DKc + fc;
        const float* vp = Vg + (size_t)(kt * 64 + fr) * DKc + fc;
#pragma unroll
        for (int it = 0; it < 8; it++) {
            cp16(sptr(&KS(st, fr + it * 8, fc)), kp + (size_t)it * 8 * DKc);
            cp16(sptr(&VS(st, fr + it * 8, fc)), vp + (size_t)it * 8 * DKc);
        }
    };

    // Q A-fragments in registers (pre-scaled + pre-tf32 by projection epilogue)
    uint32_t qa[8][2][4];
#pragma unroll
    for (int mt = 0; mt < 2; mt++) {
        const float* q0p = Qg + (size_t)(q0 + warp * 32 + mt * 16 + lq) * DKc;
        const float* q1p = q0p + (size_t)8 * DKc;
#pragma unroll
        for (int ks = 0; ks < 8; ks++) {
            qa[ks][mt][0] = fu(q0p[ks * 8 + lr]);
            qa[ks][mt][1] = fu(q1p[ks * 8 + lr]);
            qa[ks][mt][2] = fu(q0p[ks * 8 + lr + 4]);
            qa[ks][mt][3] = fu(q1p[ks * 8 + lr + 4]);
        }
    }

    float o[2][8][4];
#pragma unroll
    for (int mt = 0; mt < 2; mt++)
#pragma unroll
        for (int nf = 0; nf < 8; nf++)
#pragma unroll
            for (int j = 0; j < 4; j++) o[mt][nf][j] = 0.0f;
    float m_i[2][2] = {{-1e30f, -1e30f}, {-1e30f, -1e30f}};
    float l_i[2][2] = {{0.0f, 0.0f}, {0.0f, 0.0f}};

    const int src0 = (lane & ~3) | (lr >> 1);
    const int src1 = src0 + 2;
    const bool oddl = (lr & 1) != 0;

    // Warp's diagonal KV tile; block iterates kt = 0 .. ktmax = 2*qb+1.
    const int ktd   = 2 * qb + (warp >> 1);
    const int ktmax = 2 * qb + 1;
    const int rowl0 = 32 * (warp & 1) + lq;   // within-tile row base (mt=0)

    fill(0, 0); cp_commit();

    for (int kt = 0; kt <= ktmax; kt++) {
        const int st = kt & 1;
        cp_wait<0>();
        __syncthreads();
        if (kt < ktmax) { fill(kt + 1, st ^ 1); cp_commit(); }

        if (kt <= ktd) {
            // ---- S = Q @ K^T (warp: 32x64) ----
            float s[2][8][4];
#pragma unroll
            for (int mt = 0; mt < 2; mt++)
#pragma unroll
                for (int nf = 0; nf < 8; nf++)
#pragma unroll
                    for (int j = 0; j < 4; j++) s[mt][nf][j] = 0.0f;

#pragma unroll
            for (int ks = 0; ks < 8; ks++) {
#pragma unroll
                for (int nf = 0; nf < 8; nf++) {
                    uint32_t b0 = fu(KS(st, nf * 8 + lq, ks * 8 + lr));
                    uint32_t b1 = fu(KS(st, nf * 8 + lq, ks * 8 + lr + 4));
                    mma8(s[0][nf], qa[ks][0], b0, b1);
                    mma8(s[1][nf], qa[ks][1], b0, b1);
                }
            }

            // ---- causal mask on this warp's diagonal tile ----
            if (kt == ktd) {
#pragma unroll
                for (int mt = 0; mt < 2; mt++)
#pragma unroll
                    for (int nf = 0; nf < 8; nf++)
#pragma unroll
                        for (int j = 0; j < 4; j++) {
                            int colg = nf * 8 + 2 * lr + (j & 1);
                            int rowg = rowl0 + mt * 16 + 8 * (j >> 1);
                            if (colg > rowg) s[mt][nf][j] = -1e30f;
                        }
            }

            // ---- online softmax (per mt: rows lq and lq+8) ----
#pragma unroll
            for (int mt = 0; mt < 2; mt++)
#pragma unroll
                for (int rp = 0; rp < 2; rp++) {
                    float mx = -1e30f;
#pragma unroll
                    for (int nf = 0; nf < 8; nf++)
                        mx = fmaxf(mx, fmaxf(s[mt][nf][2 * rp], s[mt][nf][2 * rp + 1]));
                    mx = fmaxf(mx, __shfl_xor_sync(0xffffffffu, mx, 1));
                    mx = fmaxf(mx, __shfl_xor_sync(0xffffffffu, mx, 2));
                    float mnew = fmaxf(m_i[mt][rp], mx);
                    float corr = __expf(m_i[mt][rp] - mnew);
                    m_i[mt][rp] = mnew;
                    float rs = 0.0f;
#pragma unroll
                    for (int nf = 0; nf < 8; nf++) {
                        float p0 = f2tf(__expf(s[mt][nf][2 * rp]     - mnew));
                        float p1 = f2tf(__expf(s[mt][nf][2 * rp + 1] - mnew));
                        s[mt][nf][2 * rp]     = p0;
                        s[mt][nf][2 * rp + 1] = p1;
                        rs += p0 + p1;
                    }
                    rs += __shfl_xor_sync(0xffffffffu, rs, 1);
                    rs += __shfl_xor_sync(0xffffffffu, rs, 2);
                    l_i[mt][rp] = l_i[mt][rp] * corr + rs;
#pragma unroll
                    for (int nf = 0; nf < 8; nf++) {
                        o[mt][nf][2 * rp]     *= corr;
                        o[mt][nf][2 * rp + 1] *= corr;
                    }
                }

            // ---- O += P @ V (P c-frag -> A-frag via shfl) ----
#pragma unroll
            for (int ks = 0; ks < 8; ks++) {
                uint32_t pa[2][4];
#pragma unroll
                for (int mt = 0; mt < 2; mt++) {
                    float p0 = s[mt][ks][0], p1 = s[mt][ks][1];
                    float p2 = s[mt][ks][2], p3 = s[mt][ks][3];
                    float t00 = __shfl_sync(0xffffffffu, p0, src0);
                    float t01 = __shfl_sync(0xffffffffu, p1, src0);
                    float t20 = __shfl_sync(0xffffffffu, p2, src0);
                    float t21 = __shfl_sync(0xffffffffu, p3, src0);
                    float u00 = __shfl_sync(0xffffffffu, p0, src1);
                    float u01 = __shfl_sync(0xffffffffu, p1, src1);
                    float u20 = __shfl_sync(0xffffffffu, p2, src1);
                    float u21 = __shfl_sync(0xffffffffu, p3, src1);
                    pa[mt][0] = fu(oddl ? t01 : t00);
                    pa[mt][1] = fu(oddl ? t21 : t20);
                    pa[mt][2] = fu(oddl ? u01 : u00);
                    pa[mt][3] = fu(oddl ? u21 : u20);
                }
#pragma unroll
                for (int nf = 0; nf < 8; nf++) {
                    uint32_t b0 = fu(VS(st, ks * 8 + lr,     nf * 8 + lq));
                    uint32_t b1 = fu(VS(st, ks * 8 + lr + 4, nf * 8 + lq));
                    mma8(o[0][nf], pa[0], b0, b1);
                    mma8(o[1][nf], pa[1], b0, b1);
                }
            }
        }
    }

    // ---- normalize, write merged-head [B,S,D] (tf32 for the final GEMM) ----
    const int b = bh / Hc, h = bh % Hc;
#pragma unroll
    for (int mt = 0; mt < 2; mt++)
#pragma unroll
        for (int rp = 0; rp < 2; rp++) {
            float inv = 1.0f / l_i[mt][rp];
            int row = q0 + warp * 32 + mt * 16 + lq + rp * 8;
            float* dst = O + ((size_t)(b * Sc + row)) * Dc + h * DKc;
#pragma unroll
            for (int nf = 0; nf < 8; nf++) {
                float2 v = {f2tf(o[mt][nf][2 * rp] * inv),
                            f2tf(o[mt][nf][2 * rp + 1] * inv)};
                *(float2*)&dst[nf * 8 + 2 * lr] = v;
            }
        }
#undef KS
#undef VS
}

// ---------------------------------------------------------------------------
// Launch
// ---------------------------------------------------------------------------
extern "C" void kernel_launch(void* const* d_in, const int* in_sizes, int n_in,
                              void* d_out, int out_size)
{
    (void)in_sizes; (void)n_in; (void)out_size;

    const float* q  = (const float*)d_in[0];
    const float* k  = (const float*)d_in[1];
    const float* v  = (const float*)d_in[2];
    // d_in[3] = mask: causal tril, applied analytically
    const float* Wq = (const float*)d_in[4];
    const float* bq = (const float*)d_in[5];
    const float* Wk = (const float*)d_in[6];
    const float* bk = (const float*)d_in[7];
    const float* Wv = (const float*)d_in[8];
    const float* bv = (const float*)d_in[9];
    const float* Wo = (const float*)d_in[10];
    const float* bo = (const float*)d_in[11];

    float *gtf, *gq, *gk, *gv, *gat;
    cudaGetSymbolAddress((void**)&gtf, g_tf);
    cudaGetSymbolAddress((void**)&gq,  g_Q);
    cudaGetSymbolAddress((void**)&gk,  g_K);
    cudaGetSymbolAddress((void**)&gv,  g_V);
    cudaGetSymbolAddress((void**)&gat, g_attn);

    prepass<<<2880, 256>>>((const float4*)q, (const float4*)k, (const float4*)v,
                           (const float4*)Wq, (const float4*)Wk,
                           (const float4*)Wv, (const float4*)Wo, (float4*)gtf);

    const float* tq  = gtf;
    const float* tk  = gtf + NQ;
    const float* tv  = gtf + 2 * NQ;
    const float* tWq = gtf + 3 * NQ;
    const float* tWk = tWq + NW;
    const float* tWv = tWk + NW;
    const float* tWo = tWv + NW;

    // smem sizes (2-stage pipelines)
    const int gsm4 = 2 * (128 * 36 + 32 * 136) * (int)sizeof(float); // 71680
    const int gsm2 = 2 * (64 * 36 + 32 * 136) * (int)sizeof(float);  // 53248
    const int asm2 = 2 * (64 * 68 + 64 * 72) * (int)sizeof(float);   // 71680

    cudaFuncSetAttribute(gemm_qkv, cudaFuncAttributeMaxDynamicSharedMemorySize, gsm4);
    cudaFuncSetAttribute(gemm_out, cudaFuncAttributeMaxDynamicSharedMemorySize, gsm2);
    cudaFuncSetAttribute(attn_tc,  cudaFuncAttributeMaxDynamicSharedMemorySize, asm2);

    // Fused Q/K/V projections: 32 x 6 x 3 = 576 blocks, 2 CTAs/SM
    gemm_qkv<<<dim3(Mrows / 128, Dc / 128, 3), 128, gsm4>>>(
        tq, tk, tv, tWq, tWk, tWv, bq, bk, bv, gq, gk, gv);

    attn_tc<<<dim3(Sc / 128, Bc * Hc), 128, asm2>>>(gq, gk, gv, gat);

    // Final projection: 64 x 6 = 384 blocks, 3 CTAs/SM -> single wave
    gemm_out<<<dim3(Mrows / 64, Dc / 128), 128, gsm2>>>(gat, tWo, bo, (float*)d_out);
}

// round 17
// speedup vs baseline: 1.1939x; 1.0180x over previous
#include <cuda_runtime.h>
#include <cstdint>
#include <cstddef>

// Fixed problem sizes: B=2, S=2048, D=768, H=12, DK=64
constexpr int Bc  = 2;
constexpr int Sc  = 2048;
constexpr int Dc  = 768;
constexpr int Hc  = 12;
constexpr int DKc = 64;
constexpr int Mrows = Bc * Sc;   // 4096

constexpr int NQ = Mrows * Dc;   // 3145728 floats per activation tensor
constexpr int NW = Dc * Dc;      // 589824 floats per weight matrix

// Scratch (device globals: allocation-free per harness rules)
__device__ float g_tf[3 * NQ + 4 * NW];       // tf32-rounded q,k,v,Wq,Wk,Wv,Wo
__device__ float g_Q[Bc * Hc * Sc * DKc];     // [B,H,S,DK], tf32+scaled
__device__ float g_K[Bc * Hc * Sc * DKc];     // tf32
__device__ float g_V[Bc * Hc * Sc * DKc];     // tf32
__device__ float g_attn[Mrows * Dc];          // [B,S,D], tf32

// ---------------------------------------------------------------------------
// helpers
// ---------------------------------------------------------------------------
__device__ __forceinline__ float f2tf(float f) {
    uint32_t u;
    asm("cvt.rna.tf32.f32 %0, %1;" : "=r"(u) : "f"(f));
    return __uint_as_float(u);
}
__device__ __forceinline__ uint32_t fu(float f) { return __float_as_uint(f); }
__device__ __forceinline__ uint32_t sptr(const void* p) {
    return (uint32_t)__cvta_generic_to_shared(p);
}
__device__ __forceinline__ void cp16(uint32_t dst, const void* src) {
    asm volatile("cp.async.cg.shared.global [%0], [%1], 16;\n" :: "r"(dst), "l"(src));
}
__device__ __forceinline__ void cp_commit() {
    asm volatile("cp.async.commit_group;\n");
}
template <int N>
__device__ __forceinline__ void cp_wait() {
    asm volatile("cp.async.wait_group %0;\n" :: "n"(N));
}

// C += A(16x8) * B(8x8), tf32 operands, fp32 accumulate.
__device__ __forceinline__ void mma8(float* c, const uint32_t* a,
                                     uint32_t b0, uint32_t b1) {
    asm volatile(
        "mma.sync.aligned.m16n8k8.row.col.f32.tf32.tf32.f32 "
        "{%0,%1,%2,%3}, {%4,%5,%6,%7}, {%8,%9}, {%0,%1,%2,%3};\n"
        : "+f"(c[0]), "+f"(c[1]), "+f"(c[2]), "+f"(c[3])
        : "r"(a[0]), "r"(a[1]), "r"(a[2]), "r"(a[3]), "r"(b0), "r"(b1));
}

// ---------------------------------------------------------------------------
// Pre-pass: tf32-round q,k,v,Wq,Wk,Wv,Wo into g_tf (float4 grid-stride)
// ---------------------------------------------------------------------------
__global__ __launch_bounds__(256)
void prepass(const float4* __restrict__ q, const float4* __restrict__ k,
             const float4* __restrict__ v, const float4* __restrict__ wq,
             const float4* __restrict__ wk, const float4* __restrict__ wv,
             const float4* __restrict__ wo, float4* __restrict__ dst)
{
    constexpr int NQ4 = NQ / 4;
    constexpr int NW4 = NW / 4;
    constexpr int TOT = 3 * NQ4 + 4 * NW4;
    for (int i = blockIdx.x * blockDim.x + threadIdx.x; i < TOT;
         i += gridDim.x * blockDim.x) {
        const float4* src; int off;
        if (i < NQ4)            { src = q;  off = i; }
        else if (i < 2 * NQ4)   { src = k;  off = i - NQ4; }
        else if (i < 3 * NQ4)   { src = v;  off = i - 2 * NQ4; }
        else {
            int j = i - 3 * NQ4;
            int w = j / NW4; off = j - w * NW4;
            src = (w == 0) ? wq : (w == 1) ? wk : (w == 2) ? wv : wo;
        }
        float4 x = src[off];
        dst[i] = {f2tf(x.x), f2tf(x.y), f2tf(x.z), f2tf(x.w)};
    }
}

// ---------------------------------------------------------------------------
// GEMM core (tf32 mma, 2-stage cp.async, BK=32, 1 sync/iter).
// 128 threads = 4 warps laid out 2(m) x 2(n); warp tile (MT*16) x 64.
// MT=4 -> BM=128 (qkv), MT=2 -> BM=64 (final).
// EPI 0: head-split [B,H,S,DK], tf32 out   (K/V projections)
// EPI 2: head-split, * rsqrt(768), tf32 out (Q projection)
// EPI 1: row-major, ReLU, fp32 out          (final)
// ---------------------------------------------------------------------------
template <int MT>
__device__ __forceinline__
void gemm_body(const float* __restrict__ X, const float* __restrict__ W,
               const float* __restrict__ bias, float* __restrict__ out,
               int m0, int n0, int epi, float* sm)
{
    constexpr int BM  = MT * 32;
    constexpr int ASZ = BM * 36;       // stage size (floats), A stride 36
    constexpr int BSZ = 32 * 136;      // stage size (floats), B stride 136
    float* AsB = sm;                   // [2][BM][36]
    float* BsB = sm + 2 * ASZ;         // [2][32][136]
#define GA(st, r, c) AsB[(st) * ASZ + (r) * 36 + (c)]
#define GB(st, r, c) BsB[(st) * BSZ + (r) * 136 + (c)]

    const int tid  = threadIdx.x;
    const int lane = tid & 31;
    const int warp = tid >> 5;          // 0..3
    const int lq   = lane >> 2;
    const int lr   = lane & 3;
    const int wm   = (warp & 1) * (MT * 16);
    const int wn   = (warp >> 1) * 64;

    auto fill = [&](int i, int st) {
        // A: BM x 32 floats = BM*8 float4 chunks over 128 threads
#pragma unroll
        for (int it = 0; it < BM / 16; it++) {
            int idx = tid + it * 128;
            int r = idx >> 3, c = (idx & 7) * 4;
            cp16(sptr(&GA(st, r, c)), X + (size_t)(m0 + r) * Dc + i * 32 + c);
        }
        // B: 32 x 128 floats = 1024 float4 chunks over 128 threads
#pragma unroll
        for (int it = 0; it < 8; it++) {
            int idx = tid + it * 128;
            int kk = idx >> 5, n = (idx & 31) * 4;
            cp16(sptr(&GB(st, kk, n)), W + (size_t)(i * 32 + kk) * Dc + n0 + n);
        }
    };

    float c[MT][8][4];
#pragma unroll
    for (int mt = 0; mt < MT; mt++)
#pragma unroll
        for (int nt = 0; nt < 8; nt++)
#pragma unroll
            for (int j = 0; j < 4; j++) c[mt][nt][j] = 0.0f;

    fill(0, 0); cp_commit();

    constexpr int NIT = Dc / 32;   // 24
    for (int i = 0; i < NIT; i++) {
        const int st = i & 1;
        cp_wait<0>();
        __syncthreads();
        if (i + 1 < NIT) { fill(i + 1, st ^ 1); cp_commit(); }

#pragma unroll
        for (int ks = 0; ks < 32; ks += 8) {
            uint32_t a[MT][4], b[8][2];
#pragma unroll
            for (int mt = 0; mt < MT; mt++) {
                int r = wm + mt * 16 + lq;
                a[mt][0] = fu(GA(st, r,     ks + lr));
                a[mt][1] = fu(GA(st, r + 8, ks + lr));
                a[mt][2] = fu(GA(st, r,     ks + lr + 4));
                a[mt][3] = fu(GA(st, r + 8, ks + lr + 4));
            }
#pragma unroll
            for (int nt = 0; nt < 8; nt++) {
                int n = wn + nt * 8 + lq;
                b[nt][0] = fu(GB(st, ks + lr,     n));
                b[nt][1] = fu(GB(st, ks + lr + 4, n));
            }
#pragma unroll
            for (int mt = 0; mt < MT; mt++)
#pragma unroll
                for (int nt = 0; nt < 8; nt++)
                    mma8(c[mt][nt], a[mt], b[nt][0], b[nt][1]);
        }
    }

    const float qscale = rsqrtf((float)Dc);
#pragma unroll
    for (int mt = 0; mt < MT; mt++) {
        int r0 = m0 + wm + mt * 16 + lq;
#pragma unroll
        for (int nt = 0; nt < 8; nt++) {
            int col = n0 + wn + nt * 8 + 2 * lr;
            float2 bv = *(const float2*)&bias[col];
            const float* cc = c[mt][nt];
            if (epi != 1) {
                int h = col >> 6, dk = col & 63;
#pragma unroll
                for (int rp = 0; rp < 2; rp++) {
                    int r = r0 + rp * 8;
                    int bb = r >> 11, s = r & (Sc - 1);
                    float x0 = cc[2 * rp]     + bv.x;
                    float x1 = cc[2 * rp + 1] + bv.y;
                    if (epi == 2) { x0 *= qscale; x1 *= qscale; }
                    float2 v = {f2tf(x0), f2tf(x1)};
                    *(float2*)&out[(((size_t)(bb * Hc + h) * Sc + s) << 6) + dk] = v;
                }
            } else {
                float2 v0 = {fmaxf(cc[0] + bv.x, 0.0f), fmaxf(cc[1] + bv.y, 0.0f)};
                float2 v1 = {fmaxf(cc[2] + bv.x, 0.0f), fmaxf(cc[3] + bv.y, 0.0f)};
                *(float2*)&out[(size_t)r0 * Dc + col]       = v0;
                *(float2*)&out[(size_t)(r0 + 8) * Dc + col] = v1;
            }
        }
    }
#undef GA
#undef GB
}

// Fused Q/K/V projections (128x128 tiles): blockIdx.z selects the GEMM.
__global__ __launch_bounds__(128, 2)
void gemm_qkv(const float* __restrict__ Xq, const float* __restrict__ Xk,
              const float* __restrict__ Xv,
              const float* __restrict__ Wq, const float* __restrict__ Wk,
              const float* __restrict__ Wv,
              const float* __restrict__ bq, const float* __restrict__ bk,
              const float* __restrict__ bv,
              float* __restrict__ Oq, float* __restrict__ Ok,
              float* __restrict__ Ov)
{
    extern __shared__ float sm[];
    const int z = blockIdx.z;
    const float* X = (z == 0) ? Xq : (z == 1) ? Xk : Xv;
    const float* W = (z == 0) ? Wq : (z == 1) ? Wk : Wv;
    const float* b = (z == 0) ? bq : (z == 1) ? bk : bv;
    float* O       = (z == 0) ? Oq : (z == 1) ? Ok : Ov;
    gemm_body<4>(X, W, b, O, blockIdx.x * 128, blockIdx.y * 128,
                 (z == 0) ? 2 : 0, sm);
}

// Final projection: 64x128 tiles, 3 CTAs/SM -> 384 blocks in one wave. ReLU.
__global__ __launch_bounds__(128, 3)
void gemm_out(const float* __restrict__ X, const float* __restrict__ W,
              const float* __restrict__ bias, float* __restrict__ out)
{
    extern __shared__ float sm[];
    gemm_body<2>(X, W, bias, out, blockIdx.x * 64, blockIdx.y * 128, 1, sm);
}

// ---------------------------------------------------------------------------
// Flash attention, tf32 mma, 2-stage cp.async K/V, 1 sync/tile.
// 128 threads = 4 warps; BQ=128; warp w owns q-rows [q0+32w, q0+32w+32)
// as two 16-row m-frags. Q A-fragments in registers; KV tiles of 64;
// warp-level causal skipping; V natural [kv][dk] layout (== B-fragment);
// P c-frag -> A-frag via shfl (no smem round-trip).
// ---------------------------------------------------------------------------
__global__ __launch_bounds__(128, 2)
void attn_tc(const float* __restrict__ Q, const float* __restrict__ K,
             const float* __restrict__ V, float* __restrict__ O)
{
    extern __shared__ float sm[];
    float* KsB = sm;                         // [2][64][68]
    float* VsB = sm + 2 * 64 * 68;           // [2][64][72]
#define KS(st, r, c) KsB[(st) * 4352 + (r) * 68 + (c)]
#define VS(st, r, c) VsB[(st) * 4608 + (r) * 72 + (c)]

    const int tid  = threadIdx.x;
    const int lane = tid & 31;
    const int warp = tid >> 5;               // 0..3
    const int lq   = lane >> 2;
    const int lr   = lane & 3;
    const int qb   = gridDim.x - 1 - blockIdx.x;   // long blocks first
    const int bh   = blockIdx.y;
    const int q0   = qb * 128;

    const float* Qg = Q + (size_t)bh * Sc * DKc;
    const float* Kg = K + (size_t)bh * Sc * DKc;
    const float* Vg = V + (size_t)bh * Sc * DKc;

    const int fr = tid >> 4;            // 0..7  (fill row base)
    const int fc = (tid & 15) * 4;      // 0..60 (fill col)

    auto fill = [&](int kt, int st) {
        const float* kp = Kg + (size_t)(kt * 64 + fr) * DKc + fc;
        const float* vp = Vg + (size_t)(kt * 64 + fr) * DKc + fc;
#pragma unroll
        for (int it = 0; it < 8; it++) {
            cp16(sptr(&KS(st, fr + it * 8, fc)), kp + (size_t)it * 8 * DKc);
            cp16(sptr(&VS(st, fr + it * 8, fc)), vp + (size_t)it * 8 * DKc);
        }
    };

    // Q A-fragments in registers (pre-scaled + pre-tf32 by projection epilogue)
    uint32_t qa[8][2][4];
#pragma unroll
    for (int mt = 0; mt < 2; mt++) {
        const float* q0p = Qg + (size_t)(q0 + warp * 32 + mt * 16 + lq) * DKc;
        const float* q1p = q0p + (size_t)8 * DKc;
#pragma unroll
        for (int ks = 0; ks < 8; ks++) {
            qa[ks][mt][0] = fu(q0p[ks * 8 + lr]);
            qa[ks][mt][1] = fu(q1p[ks * 8 + lr]);
            qa[ks][mt][2] = fu(q0p[ks * 8 + lr + 4]);
            qa[ks][mt][3] = fu(q1p[ks * 8 + lr + 4]);
        }
    }

    float o[2][8][4];
#pragma unroll
    for (int mt = 0; mt < 2; mt++)
#pragma unroll
        for (int nf = 0; nf < 8; nf++)
#pragma unroll
            for (int j = 0; j < 4; j++) o[mt][nf][j] = 0.0f;
    float m_i[2][2] = {{-1e30f, -1e30f}, {-1e30f, -1e30f}};
    float l_i[2][2] = {{0.0f, 0.0f}, {0.0f, 0.0f}};

    const int src0 = (lane & ~3) | (lr >> 1);
    const int src1 = src0 + 2;
    const bool oddl = (lr & 1) != 0;

    // Warp's diagonal KV tile; block iterates kt = 0 .. ktmax = 2*qb+1.
    const int ktd   = 2 * qb + (warp >> 1);
    const int ktmax = 2 * qb + 1;
    const int rowl0 = 32 * (warp & 1) + lq;   // within-tile row base (mt=0)

    fill(0, 0); cp_commit();

    for (int kt = 0; kt <= ktmax; kt++) {
        const int st = kt & 1;
        cp_wait<0>();
        __syncthreads();
        if (kt < ktmax) { fill(kt + 1, st ^ 1); cp_commit(); }

        if (kt <= ktd) {
            // ---- S = Q @ K^T (warp: 32x64) ----
            float s[2][8][4];
#pragma unroll
            for (int mt = 0; mt < 2; mt++)
#pragma unroll
                for (int nf = 0; nf < 8; nf++)
#pragma unroll
                    for (int j = 0; j < 4; j++) s[mt][nf][j] = 0.0f;

#pragma unroll
            for (int ks = 0; ks < 8; ks++) {
#pragma unroll
                for (int nf = 0; nf < 8; nf++) {
                    uint32_t b0 = fu(KS(st, nf * 8 + lq, ks * 8 + lr));
                    uint32_t b1 = fu(KS(st, nf * 8 + lq, ks * 8 + lr + 4));
                    mma8(s[0][nf], qa[ks][0], b0, b1);
                    mma8(s[1][nf], qa[ks][1], b0, b1);
                }
            }

            // ---- causal mask on this warp's diagonal tile ----
            if (kt == ktd) {
#pragma unroll
                for (int mt = 0; mt < 2; mt++)
#pragma unroll
                    for (int nf = 0; nf < 8; nf++)
#pragma unroll
                        for (int j = 0; j < 4; j++) {
                            int colg = nf * 8 + 2 * lr + (j & 1);
                            int rowg = rowl0 + mt * 16 + 8 * (j >> 1);
                            if (colg > rowg) s[mt][nf][j] = -1e30f;
                        }
            }

            // ---- online softmax (per mt: rows lq and lq+8) ----
#pragma unroll
            for (int mt = 0; mt < 2; mt++)
#pragma unroll
                for (int rp = 0; rp < 2; rp++) {
                    float mx = -1e30f;
#pragma unroll
                    for (int nf = 0; nf < 8; nf++)
                        mx = fmaxf(mx, fmaxf(s[mt][nf][2 * rp], s[mt][nf][2 * rp + 1]));
                    mx = fmaxf(mx, __shfl_xor_sync(0xffffffffu, mx, 1));
                    mx = fmaxf(mx, __shfl_xor_sync(0xffffffffu, mx, 2));
                    float mnew = fmaxf(m_i[mt][rp], mx);
                    float corr = __expf(m_i[mt][rp] - mnew);
                    m_i[mt][rp] = mnew;
                    float rs = 0.0f;
#pragma unroll
                    for (int nf = 0; nf < 8; nf++) {
                        float p0 = f2tf(__expf(s[mt][nf][2 * rp]     - mnew));
                        float p1 = f2tf(__expf(s[mt][nf][2 * rp + 1] - mnew));
                        s[mt][nf][2 * rp]     = p0;
                        s[mt][nf][2 * rp + 1] = p1;
                        rs += p0 + p1;
                    }
                    rs += __shfl_xor_sync(0xffffffffu, rs, 1);
                    rs += __shfl_xor_sync(0xffffffffu, rs, 2);
                    l_i[mt][rp] = l_i[mt][rp] * corr + rs;
#pragma unroll
                    for (int nf = 0; nf < 8; nf++) {
                        o[mt][nf][2 * rp]     *= corr;
                        o[mt][nf][2 * rp + 1] *= corr;
                    }
                }

            // ---- O += P @ V (P c-frag -> A-frag via shfl) ----
#pragma unroll
            for (int ks = 0; ks < 8; ks++) {
                uint32_t pa[2][4];
#pragma unroll
                for (int mt = 0; mt < 2; mt++) {
                    float p0 = s[mt][ks][0], p1 = s[mt][ks][1];
                    float p2 = s[mt][ks][2], p3 = s[mt][ks][3];
                    float t00 = __shfl_sync(0xffffffffu, p0, src0);
                    float t01 = __shfl_sync(0xffffffffu, p1, src0);
                    float t20 = __shfl_sync(0xffffffffu, p2, src0);
                    float t21 = __shfl_sync(0xffffffffu, p3, src0);
                    float u00 = __shfl_sync(0xffffffffu, p0, src1);
                    float u01 = __shfl_sync(0xffffffffu, p1, src1);
                    float u20 = __shfl_sync(0xffffffffu, p2, src1);
                    float u21 = __shfl_sync(0xffffffffu, p3, src1);
                    pa[mt][0] = fu(oddl ? t01 : t00);
                    pa[mt][1] = fu(oddl ? t21 : t20);
                    pa[mt][2] = fu(oddl ? u01 : u00);
                    pa[mt][3] = fu(oddl ? u21 : u20);
                }
#pragma unroll
                for (int nf = 0; nf < 8; nf++) {
                    uint32_t b0 = fu(VS(st, ks * 8 + lr,     nf * 8 + lq));
                    uint32_t b1 = fu(VS(st, ks * 8 + lr + 4, nf * 8 + lq));
                    mma8(o[0][nf], pa[0], b0, b1);
                    mma8(o[1][nf], pa[1], b0, b1);
                }
            }
        }
    }

    // ---- normalize, write merged-head [B,S,D] (tf32 for the final GEMM) ----
    const int b = bh / Hc, h = bh % Hc;
#pragma unroll
    for (int mt = 0; mt < 2; mt++)
#pragma unroll
        for (int rp = 0; rp < 2; rp++) {
            float inv = 1.0f / l_i[mt][rp];
            int row = q0 + warp * 32 + mt * 16 + lq + rp * 8;
            float* dst = O + ((size_t)(b * Sc + row)) * Dc + h * DKc;
#pragma unroll
            for (int nf = 0; nf < 8; nf++) {
                float2 v = {f2tf(o[mt][nf][2 * rp] * inv),
                            f2tf(o[mt][nf][2 * rp + 1] * inv)};
                *(float2*)&dst[nf * 8 + 2 * lr] = v;
            }
        }
#undef KS
#undef VS
}

// ---------------------------------------------------------------------------
// Launch
// ---------------------------------------------------------------------------
extern "C" void kernel_launch(void* const* d_in, const int* in_sizes, int n_in,
                              void* d_out, int out_size)
{
    (void)in_sizes; (void)n_in; (void)out_size;

    const float* q  = (const float*)d_in[0];
    const float* k  = (const float*)d_in[1];
    const float* v  = (const float*)d_in[2];
    // d_in[3] = mask: causal tril, applied analytically
    const float* Wq = (const float*)d_in[4];
    const float* bq = (const float*)d_in[5];
    const float* Wk = (const float*)d_in[6];
    const float* bk = (const float*)d_in[7];
    const float* Wv = (const float*)d_in[8];
    const float* bv = (const float*)d_in[9];
    const float* Wo = (const float*)d_in[10];
    const float* bo = (const float*)d_in[11];

    float *gtf, *gq, *gk, *gv, *gat;
    cudaGetSymbolAddress((void**)&gtf, g_tf);
    cudaGetSymbolAddress((void**)&gq,  g_Q);
    cudaGetSymbolAddress((void**)&gk,  g_K);
    cudaGetSymbolAddress((void**)&gv,  g_V);
    cudaGetSymbolAddress((void**)&gat, g_attn);

    prepass<<<2880, 256>>>((const float4*)q, (const float4*)k, (const float4*)v,
                           (const float4*)Wq, (const float4*)Wk,
                           (const float4*)Wv, (const float4*)Wo, (float4*)gtf);

    const float* tq  = gtf;
    const float* tk  = gtf + NQ;
    const float* tv  = gtf + 2 * NQ;
    const float* tWq = gtf + 3 * NQ;
    const float* tWk = tWq + NW;
    const float* tWv = tWk + NW;
    const float* tWo = tWv + NW;

    // smem sizes (2-stage pipelines)
    const int gsm4 = 2 * (128 * 36 + 32 * 136) * (int)sizeof(float); // 71680
    const int gsm2 = 2 * (64 * 36 + 32 * 136) * (int)sizeof(float);  // 53248
    const int asm2 = 2 * (64 * 68 + 64 * 72) * (int)sizeof(float);   // 71680

    cudaFuncSetAttribute(gemm_qkv, cudaFuncAttributeMaxDynamicSharedMemorySize, gsm4);
    cudaFuncSetAttribute(gemm_out, cudaFuncAttributeMaxDynamicSharedMemorySize, gsm2);
    cudaFuncSetAttribute(attn_tc,  cudaFuncAttributeMaxDynamicSharedMemorySize, asm2);

    // Fused Q/K/V projections: 32 x 6 x 3 = 576 blocks, 2 CTAs/SM
    gemm_qkv<<<dim3(Mrows / 128, Dc / 128, 3), 128, gsm4>>>(
        tq, tk, tv, tWq, tWk, tWv, bq, bk, bv, gq, gk, gv);

    attn_tc<<<dim3(Sc / 128, Bc * Hc), 128, asm2>>>(gq, gk, gv, gat);

    // Final projection: 64 x 6 = 384 blocks, 3 CTAs/SM -> single wave
    gemm_out<<<dim3(Mrows / 64, Dc / 128), 128, gsm2>>>(gat, tWo, bo, (float*)d_out);
}